// round 8
// baseline (speedup 1.0000x reference)
#include <cuda_runtime.h>
#include <math.h>
#include <stdint.h>

// ---------------------------------------------------------------------------
// Scratch (no cudaMalloc allowed)
// ---------------------------------------------------------------------------
__device__ float g_qk[33554432];   // 32768 x 1024  (Q | K) tf32-rounded
__device__ float g_ao[16777216];   // 32768 x 512   attention output (tf32-rounded)
__device__ float g_wc[524288];     // 1024 x 512    w_qkv rows 0..1023, tf32-rounded
__device__ float g_wo[262144];     // 512 x 512     w_out, tf32-rounded

__device__ __forceinline__ float rtf32(float v) {  // round-to-nearest tf32
    uint32_t r;
    asm("cvt.rna.tf32.f32 %0, %1;" : "=r"(r) : "f"(v));
    return __uint_as_float(r);
}
__device__ __forceinline__ uint32_t rtf32u(uint32_t v) {
    uint32_t r;
    asm("cvt.rna.tf32.f32 %0, %1;" : "=r"(r) : "f"(__uint_as_float(v)));
    return r;
}
__device__ __forceinline__ uint32_t smem_u32(const void* p) {
    uint32_t a;
    asm("{ .reg .u64 t; cvta.to.shared.u64 t, %1; cvt.u32.u64 %0, t; }"
        : "=r"(a) : "l"(p));
    return a;
}
__device__ __forceinline__ void cpa16(uint32_t s, const void* g) {
    asm volatile("cp.async.cg.shared.global [%0], [%1], 16;" :: "r"(s), "l"(g));
}
// Zero-fill variant: src-size 0 -> writes 16 zero bytes, no gmem read.
__device__ __forceinline__ void cpa16z(uint32_t s, const void* g, int sz) {
    asm volatile("cp.async.cg.shared.global [%0], [%1], 16, %2;"
                 :: "r"(s), "l"(g), "r"(sz));
}

// mma.sync m16n8k8 tf32 (baseline PTX, works on .target sm_103)
__device__ __forceinline__ void mma_tf32(float* d, const uint32_t* a,
                                         const uint32_t* b) {
    asm volatile(
        "mma.sync.aligned.m16n8k8.row.col.f32.tf32.tf32.f32 "
        "{%0,%1,%2,%3}, {%4,%5,%6,%7}, {%8,%9}, {%0,%1,%2,%3};"
        : "+f"(d[0]), "+f"(d[1]), "+f"(d[2]), "+f"(d[3])
        : "r"(a[0]), "r"(a[1]), "r"(a[2]), "r"(a[3]), "r"(b[0]), "r"(b[1]));
}

// ---------------------------------------------------------------------------
// tf32 mma.sync GEMM: C[M,N] = A[M,K] @ B[N,K]^T (+bias, optional out-round,
// optional in-register RNA rounding of A fragments).
// CTA: 128x128 tile, 256 threads = 8 warps (2x4), warp tile 64x32.
// Smem stride 36 floats; dynamic smem: 4 * 128 * 36 * 4 = 73728 B.
// ---------------------------------------------------------------------------
#define GSTR 36

__device__ __forceinline__ void load_tile36(float* dst, const float* gsrc,
                                            int K, int tid) {
#pragma unroll
    for (int l = 0; l < 4; l++) {
        int idx = tid + l * 256;        // 0..1023 (128 rows x 8 x 16B)
        int row = idx >> 3;
        int q   = idx & 7;
        cpa16(smem_u32(dst + row * GSTR + q * 4),
              gsrc + (size_t)row * K + q * 4);
    }
}

template<bool BIAS, bool ROUND_OUT, bool ROUND_A>
__global__ __launch_bounds__(256, 2)
void mma_gemm(const float* __restrict__ A, const float* __restrict__ B,
              const float* __restrict__ bias, float* __restrict__ C,
              int N, int K)
{
    extern __shared__ float sm[];
    float* Abuf[2] = {sm,          sm + 4608};
    float* Bbuf[2] = {sm + 9216,   sm + 13824};

    const int tid = threadIdx.x;
    const int wid = tid >> 5, lid = tid & 31;
    const int gid = lid >> 2, tig = lid & 3;
    const int wm = wid >> 2, wn = wid & 3;       // 2x4 warp grid, 64x32 tiles
    const int n0 = blockIdx.x * 128, m0 = blockIdx.y * 128;
    const int NC = K >> 5;

    const float* gA = A + (size_t)m0 * K;
    const float* gB = B + (size_t)n0 * K;

    float acc[4][4][4];
#pragma unroll
    for (int mt = 0; mt < 4; mt++)
#pragma unroll
        for (int nt = 0; nt < 4; nt++)
#pragma unroll
            for (int r = 0; r < 4; r++) acc[mt][nt][r] = 0.f;

    load_tile36(Abuf[0], gA, K, tid);
    load_tile36(Bbuf[0], gB, K, tid);
    asm volatile("cp.async.commit_group;" ::: "memory");

    for (int c = 0; c < NC; c++) {
        if (c + 1 < NC) {
            int nb = (c + 1) & 1;
            load_tile36(Abuf[nb], gA + (c + 1) * 32, K, tid);
            load_tile36(Bbuf[nb], gB + (c + 1) * 32, K, tid);
            asm volatile("cp.async.commit_group;" ::: "memory");
            asm volatile("cp.async.wait_group 1;" ::: "memory");
        } else {
            asm volatile("cp.async.wait_group 0;" ::: "memory");
        }
        __syncthreads();

        const float* As = Abuf[c & 1];
        const float* Bs = Bbuf[c & 1];
#pragma unroll
        for (int k8 = 0; k8 < 4; k8++) {
            const int kb = k8 * 8;
            uint32_t af[4][4], bf[4][2];
#pragma unroll
            for (int mt = 0; mt < 4; mt++) {
                const float* ap = As + (wm * 64 + mt * 16 + gid) * GSTR + kb + tig;
                af[mt][0] = __float_as_uint(ap[0]);
                af[mt][1] = __float_as_uint(ap[8 * GSTR]);
                af[mt][2] = __float_as_uint(ap[4]);
                af[mt][3] = __float_as_uint(ap[8 * GSTR + 4]);
                if (ROUND_A) {
                    af[mt][0] = rtf32u(af[mt][0]);
                    af[mt][1] = rtf32u(af[mt][1]);
                    af[mt][2] = rtf32u(af[mt][2]);
                    af[mt][3] = rtf32u(af[mt][3]);
                }
            }
#pragma unroll
            for (int nt = 0; nt < 4; nt++) {
                const float* bp = Bs + (wn * 32 + nt * 8 + gid) * GSTR + kb + tig;
                bf[nt][0] = __float_as_uint(bp[0]);
                bf[nt][1] = __float_as_uint(bp[4]);
            }
#pragma unroll
            for (int mt = 0; mt < 4; mt++)
#pragma unroll
                for (int nt = 0; nt < 4; nt++)
                    mma_tf32(acc[mt][nt], af[mt], bf[nt]);
        }
        __syncthreads();
    }

#pragma unroll
    for (int mt = 0; mt < 4; mt++) {
        int row = m0 + wm * 64 + mt * 16 + gid;
#pragma unroll
        for (int nt = 0; nt < 4; nt++) {
            int col = n0 + wn * 32 + nt * 8 + 2 * tig;
            float2 v0 = make_float2(acc[mt][nt][0], acc[mt][nt][1]);
            float2 v1 = make_float2(acc[mt][nt][2], acc[mt][nt][3]);
            if (BIAS) {
                float2 bb = *(const float2*)(bias + col);
                v0.x += bb.x; v0.y += bb.y;
                v1.x += bb.x; v1.y += bb.y;
            }
            if (ROUND_OUT) {
                v0.x = rtf32(v0.x); v0.y = rtf32(v0.y);
                v1.x = rtf32(v1.x); v1.y = rtf32(v1.y);
            }
            *(float2*)(C + (size_t)row * N + col) = v0;
            *(float2*)(C + (size_t)(row + 8) * N + col) = v1;
        }
    }
}

// ---------------------------------------------------------------------------
// Elementwise tf32 (RNA) rounding (weights only; tiny)
// ---------------------------------------------------------------------------
__global__ void round_tf32_k(const float4* __restrict__ in,
                             float4* __restrict__ out, int n4)
{
    int i = blockIdx.x * blockDim.x + threadIdx.x;
    if (i < n4) {
        float4 v = in[i];
        v.x = rtf32(v.x); v.y = rtf32(v.y);
        v.z = rtf32(v.z); v.w = rtf32(v.w);
        out[i] = v;
    }
}

// ---------------------------------------------------------------------------
// Tensor-core windowed attention (unchanged from R7). One CTA per (batch,
// window): 256 CTAs, 256 threads = 8 warps.
// ---------------------------------------------------------------------------
#define ASTR 36
#define PSTR 260

__global__ __launch_bounds__(256, 1)
void attn_mma(const float* __restrict__ qk, float* __restrict__ ao)
{
    extern __shared__ float sm[];
    float* Ps = sm;                         // 128 x 260
    float* Kt = sm + 33280;                 // 32 x 260
    float* Qb[2] = {sm,         sm + 13824};
    float* Kb[2] = {sm + 4608,  sm + 18432};

    const int tid = threadIdx.x;
    const int wid = tid >> 5, lid = tid & 31;
    const int gid = lid >> 2, tig = lid & 3;
    const int b   = blockIdx.x >> 6;
    const int wi  = blockIdx.x & 63;
    const size_t qrow0 = (size_t)b * 8192 + (size_t)wi * 128;
    const bool w0 = (wi == 0);

    // ---- Phase A: S = Q . K2^T ----
    const int wm = wid >> 2, wn = wid & 3;   // 2x4 warp grid, 64x64 tiles
    float acc[4][8][4];
#pragma unroll
    for (int mt = 0; mt < 4; mt++)
#pragma unroll
        for (int nt = 0; nt < 8; nt++)
#pragma unroll
            for (int r = 0; r < 4; r++) acc[mt][nt][r] = 0.f;

    const float* Qg = qk + qrow0 * 1024;

    auto stage = [&](int c, int bi) {
        float* sQ = Qb[bi];
        float* sK = Kb[bi];
#pragma unroll
        for (int l = 0; l < 4; l++) {
            int idx = tid + l * 256;
            int row = idx >> 3, q = idx & 7;
            cpa16(smem_u32(sQ + row * ASTR + q * 4),
                  Qg + (size_t)row * 1024 + c * 32 + q * 4);
        }
#pragma unroll
        for (int l = 0; l < 8; l++) {
            int idx = tid + l * 256;
            int row = idx >> 3, q = idx & 7;
            const float* src = qk + (qrow0 + row - 128) * 1024 + 512 + c * 32 + q * 4;
            int sz = (w0 && row < 128) ? 0 : 16;
            cpa16z(smem_u32(sK + row * ASTR + q * 4), (w0 && row < 128) ? qk : src, sz);
        }
    };

    stage(0, 0);
    asm volatile("cp.async.commit_group;" ::: "memory");

    for (int c = 0; c < 16; c++) {
        if (c + 1 < 16) {
            stage(c + 1, (c + 1) & 1);
            asm volatile("cp.async.commit_group;" ::: "memory");
            asm volatile("cp.async.wait_group 1;" ::: "memory");
        } else {
            asm volatile("cp.async.wait_group 0;" ::: "memory");
        }
        __syncthreads();

        const float* sQ = Qb[c & 1];
        const float* sK = Kb[c & 1];
#pragma unroll
        for (int k8 = 0; k8 < 4; k8++) {
            const int kb = k8 * 8;
            uint32_t af[4][4], bf[8][2];
#pragma unroll
            for (int mt = 0; mt < 4; mt++) {
                const float* ap = sQ + (wm * 64 + mt * 16 + gid) * ASTR + kb + tig;
                af[mt][0] = __float_as_uint(ap[0]);
                af[mt][1] = __float_as_uint(ap[8 * ASTR]);
                af[mt][2] = __float_as_uint(ap[4]);
                af[mt][3] = __float_as_uint(ap[8 * ASTR + 4]);
            }
#pragma unroll
            for (int nt = 0; nt < 8; nt++) {
                const float* bp = sK + (wn * 64 + nt * 8 + gid) * ASTR + kb + tig;
                bf[nt][0] = __float_as_uint(bp[0]);
                bf[nt][1] = __float_as_uint(bp[4]);
            }
#pragma unroll
            for (int mt = 0; mt < 4; mt++)
#pragma unroll
                for (int nt = 0; nt < 8; nt++)
                    mma_tf32(acc[mt][nt], af[mt], bf[nt]);
        }
        __syncthreads();
    }

    // S -> Ps
#pragma unroll
    for (int mt = 0; mt < 4; mt++) {
        int row = wm * 64 + mt * 16 + gid;
#pragma unroll
        for (int nt = 0; nt < 8; nt++) {
            int col = wn * 64 + nt * 8 + 2 * tig;
            *(float2*)(Ps + row * PSTR + col) =
                make_float2(acc[mt][nt][0], acc[mt][nt][1]);
            *(float2*)(Ps + (row + 8) * PSTR + col) =
                make_float2(acc[mt][nt][2], acc[mt][nt][3]);
        }
    }
    __syncthreads();

    // ---- softmax ----
    {
        const float scale = 0.04419417382415922f;   // 512^-0.5
        const int tr = tid >> 4, tc = tid & 15;
#pragma unroll
        for (int ri = 0; ri < 8; ri++) {
            int i = tr * 8 + ri;
            float* prow = Ps + i * PSTR;
            float vv[16];
            float mx = -3.402823466e38f;
#pragma unroll
            for (int cj = 0; cj < 16; cj++) {
                int j = cj * 16 + tc;
                float v = prow[j] * scale;
                if (j > i + 128) v = -3.402823466e38f;
                vv[cj] = v;
                mx = fmaxf(mx, v);
            }
#pragma unroll
            for (int m = 8; m >= 1; m >>= 1)
                mx = fmaxf(mx, __shfl_xor_sync(0xffffffffu, mx, m));
            float sum = 0.f;
#pragma unroll
            for (int cj = 0; cj < 16; cj++) {
                vv[cj] = __expf(vv[cj] - mx);
                sum += vv[cj];
            }
#pragma unroll
            for (int m = 8; m >= 1; m >>= 1)
                sum += __shfl_xor_sync(0xffffffffu, sum, m);
            float inv = 1.f / sum;
#pragma unroll
            for (int cj = 0; cj < 16; cj++)
                prow[cj * 16 + tc] = rtf32(vv[cj] * inv);
        }
    }
    __syncthreads();

    // ---- Phase C: O = P . K2, 16 chunks of 32 d-cols ----
    const int wm2 = wid >> 1, wn2 = wid & 1;   // 4x2 warp grid, 32x16 tiles
    for (int co = 0; co < 16; co++) {
        int c0 = co * 32;
#pragma unroll
        for (int l = 0; l < 8; l++) {
            float4 v = make_float4(0.f, 0.f, 0.f, 0.f);
            if (!(w0 && tid < 128))
                v = *(const float4*)(qk + (qrow0 + tid - 128) * 1024 + 512 + c0 + l * 4);
            Kt[(l * 4 + 0) * PSTR + tid] = v.x;
            Kt[(l * 4 + 1) * PSTR + tid] = v.y;
            Kt[(l * 4 + 2) * PSTR + tid] = v.z;
            Kt[(l * 4 + 3) * PSTR + tid] = v.w;
        }
        __syncthreads();

        float a2[2][2][4];
#pragma unroll
        for (int mt = 0; mt < 2; mt++)
#pragma unroll
            for (int nt = 0; nt < 2; nt++)
#pragma unroll
                for (int r = 0; r < 4; r++) a2[mt][nt][r] = 0.f;

#pragma unroll 4
        for (int kb = 0; kb < 256; kb += 8) {
            uint32_t af[2][4], bf[2][2];
#pragma unroll
            for (int mt = 0; mt < 2; mt++) {
                const float* ap = Ps + (wm2 * 32 + mt * 16 + gid) * PSTR + kb + tig;
                af[mt][0] = __float_as_uint(ap[0]);
                af[mt][1] = __float_as_uint(ap[8 * PSTR]);
                af[mt][2] = __float_as_uint(ap[4]);
                af[mt][3] = __float_as_uint(ap[8 * PSTR + 4]);
            }
#pragma unroll
            for (int nt = 0; nt < 2; nt++) {
                const float* bp = Kt + (wn2 * 16 + nt * 8 + gid) * PSTR + kb + tig;
                bf[nt][0] = __float_as_uint(bp[0]);
                bf[nt][1] = __float_as_uint(bp[4]);
            }
#pragma unroll
            for (int mt = 0; mt < 2; mt++)
#pragma unroll
                for (int nt = 0; nt < 2; nt++)
                    mma_tf32(a2[mt][nt], af[mt], bf[nt]);
        }

#pragma unroll
        for (int mt = 0; mt < 2; mt++) {
            size_t row = qrow0 + wm2 * 32 + mt * 16 + gid;
#pragma unroll
            for (int nt = 0; nt < 2; nt++) {
                int col = c0 + wn2 * 16 + nt * 8 + 2 * tig;
                *(float2*)(ao + row * 512 + col) =
                    make_float2(rtf32(a2[mt][nt][0]), rtf32(a2[mt][nt][1]));
                *(float2*)(ao + (row + 8) * 512 + col) =
                    make_float2(rtf32(a2[mt][nt][2]), rtf32(a2[mt][nt][3]));
            }
        }
        __syncthreads();
    }
}

// ---------------------------------------------------------------------------
extern "C" void kernel_launch(void* const* d_in, const int* in_sizes, int n_in,
                              void* d_out, int out_size)
{
    (void)in_sizes; (void)n_in; (void)out_size;
    const float* x     = (const float*)d_in[0];   // (4,8192,512)
    const float* w_qkv = (const float*)d_in[1];   // (1536,512); rows 0..1023 used
    const float* w_out = (const float*)d_in[2];   // (512,512)
    const float* b_out = (const float*)d_in[3];   // (512,)
    float* out = (float*)d_out;                   // (4,8192,512)

    float *qk, *ao, *wc, *wo;
    cudaGetSymbolAddress((void**)&qk, g_qk);
    cudaGetSymbolAddress((void**)&ao, g_ao);
    cudaGetSymbolAddress((void**)&wc, g_wc);
    cudaGetSymbolAddress((void**)&wo, g_wo);

    cudaFuncSetAttribute(attn_mma,
                         cudaFuncAttributeMaxDynamicSharedMemorySize, 166400);
    cudaFuncSetAttribute((const void*)mma_gemm<false, true, true>,
                         cudaFuncAttributeMaxDynamicSharedMemorySize, 73728);
    cudaFuncSetAttribute((const void*)mma_gemm<true, false, false>,
                         cudaFuncAttributeMaxDynamicSharedMemorySize, 73728);

    // 0) Round weights to tf32 (tiny; x is rounded in-register inside GEMM1).
    round_tf32_k<<<(131072 + 255) / 256, 256>>>((const float4*)w_qkv, (float4*)wc, 131072);
    round_tf32_k<<<(65536  + 255) / 256, 256>>>((const float4*)w_out, (float4*)wo, 65536);

    // 1) QK projection; A fragments RNA-rounded in-register; output tf32-rounded.
    {
        dim3 g(1024 / 128, 32768 / 128);
        mma_gemm<false, true, true><<<g, 256, 73728>>>(x, wc, nullptr, qk, 1024, 512);
    }

    // 2) Tensor-core windowed attention (256 windows).
    attn_mma<<<256, 256, 166400>>>(qk, ao);

    // 3) Output projection + bias (A=g_ao already tf32-rounded).
    {
        dim3 g(512 / 128, 32768 / 128);
        mma_gemm<true, false, false><<<g, 256, 73728>>>(ao, wo, b_out, out, 512, 512);
    }
}

// round 10
// speedup vs baseline: 1.1162x; 1.1162x over previous
#include <cuda_runtime.h>
#include <math.h>
#include <stdint.h>

// ---------------------------------------------------------------------------
// Scratch (no cudaMalloc allowed)
// ---------------------------------------------------------------------------
__device__ float g_qk[33554432];   // 32768 x 1024  (Q | K) tf32-rounded
__device__ float g_ao[16777216];   // 32768 x 512   attention output (tf32-rounded)
__device__ float g_wc[524288];     // 1024 x 512    w_qkv rows 0..1023, tf32-rounded
__device__ float g_wo[262144];     // 512 x 512     w_out, tf32-rounded

__device__ __forceinline__ float rtf32(float v) {  // round-to-nearest tf32
    uint32_t r;
    asm("cvt.rna.tf32.f32 %0, %1;" : "=r"(r) : "f"(v));
    return __uint_as_float(r);
}
__device__ __forceinline__ uint32_t rtf32u(uint32_t v) {
    uint32_t r;
    asm("cvt.rna.tf32.f32 %0, %1;" : "=r"(r) : "f"(__uint_as_float(v)));
    return r;
}
__device__ __forceinline__ uint32_t smem_u32(const void* p) {
    uint32_t a;
    asm("{ .reg .u64 t; cvta.to.shared.u64 t, %1; cvt.u32.u64 %0, t; }"
        : "=r"(a) : "l"(p));
    return a;
}
__device__ __forceinline__ void cpa16(uint32_t s, const void* g) {
    asm volatile("cp.async.cg.shared.global [%0], [%1], 16;" :: "r"(s), "l"(g));
}
__device__ __forceinline__ void cpa16z(uint32_t s, const void* g, int sz) {
    asm volatile("cp.async.cg.shared.global [%0], [%1], 16, %2;"
                 :: "r"(s), "l"(g), "r"(sz));
}

// mma.sync m16n8k8 tf32. k within the k8 block is PERMUTED: thread tig owns
// k = {2*tig, 2*tig+1} (contiguous -> LDS.64 fragments). Valid because the
// same permutation is applied to both A and B (k-sum is order-invariant).
__device__ __forceinline__ void mma_tf32(float* d, const uint32_t* a,
                                         const uint32_t* b) {
    asm volatile(
        "mma.sync.aligned.m16n8k8.row.col.f32.tf32.tf32.f32 "
        "{%0,%1,%2,%3}, {%4,%5,%6,%7}, {%8,%9}, {%0,%1,%2,%3};"
        : "+f"(d[0]), "+f"(d[1]), "+f"(d[2]), "+f"(d[3])
        : "r"(a[0]), "r"(a[1]), "r"(a[2]), "r"(a[3]), "r"(b[0]), "r"(b[1]));
}

// Fragment loaders (k-pair permuted, LDS.64)
__device__ __forceinline__ void load_afrag(uint32_t* af, const float* ap,
                                           int str) {
    float2 p1 = *(const float2*)ap;            // (r,   k1),(r,   k2)
    float2 p2 = *(const float2*)(ap + 8 * str);// (r+8, k1),(r+8, k2)
    af[0] = __float_as_uint(p1.x);
    af[1] = __float_as_uint(p2.x);
    af[2] = __float_as_uint(p1.y);
    af[3] = __float_as_uint(p2.y);
}
__device__ __forceinline__ void load_bfrag(uint32_t* bf, const float* bp) {
    float2 q = *(const float2*)bp;             // (k1,n),(k2,n)
    bf[0] = __float_as_uint(q.x);
    bf[1] = __float_as_uint(q.y);
}

// ---------------------------------------------------------------------------
// tf32 mma.sync GEMM: C[M,N] = A[M,K] @ B[N,K]^T.
// CTA 128x128, 256 threads = 8 warps (2x4), warp tile 64x32.
// Tile stride 40 floats (160B == 32 mod 128 -> LDS.64 conflict-free).
// Dynamic smem: 4 * 128 * 40 * 4 = 81920 B (2 CTAs/SM).
// ---------------------------------------------------------------------------
#define GSTR 40

__device__ __forceinline__ void load_tile40(float* dst, const float* gsrc,
                                            int K, int tid) {
#pragma unroll
    for (int l = 0; l < 4; l++) {
        int idx = tid + l * 256;        // 0..1023 (128 rows x 8 x 16B)
        int row = idx >> 3;
        int q   = idx & 7;
        cpa16(smem_u32(dst + row * GSTR + q * 4),
              gsrc + (size_t)row * K + q * 4);
    }
}

template<bool BIAS, bool ROUND_OUT, bool ROUND_A>
__global__ __launch_bounds__(256, 2)
void mma_gemm(const float* __restrict__ A, const float* __restrict__ B,
              const float* __restrict__ bias, float* __restrict__ C,
              int N, int K)
{
    extern __shared__ float sm[];
    float* Abuf[2] = {sm,          sm + 5120};
    float* Bbuf[2] = {sm + 10240,  sm + 15360};

    const int tid = threadIdx.x;
    const int wid = tid >> 5, lid = tid & 31;
    const int gid = lid >> 2, tig = lid & 3;
    const int wm = wid >> 2, wn = wid & 3;       // 2x4 warp grid, 64x32 tiles
    const int n0 = blockIdx.x * 128, m0 = blockIdx.y * 128;
    const int NC = K >> 5;

    const float* gA = A + (size_t)m0 * K;
    const float* gB = B + (size_t)n0 * K;

    float acc[4][4][4];
#pragma unroll
    for (int mt = 0; mt < 4; mt++)
#pragma unroll
        for (int nt = 0; nt < 4; nt++)
#pragma unroll
            for (int r = 0; r < 4; r++) acc[mt][nt][r] = 0.f;

    load_tile40(Abuf[0], gA, K, tid);
    load_tile40(Bbuf[0], gB, K, tid);
    asm volatile("cp.async.commit_group;" ::: "memory");

    for (int c = 0; c < NC; c++) {
        if (c + 1 < NC) {
            int nb = (c + 1) & 1;
            load_tile40(Abuf[nb], gA + (c + 1) * 32, K, tid);
            load_tile40(Bbuf[nb], gB + (c + 1) * 32, K, tid);
            asm volatile("cp.async.commit_group;" ::: "memory");
            asm volatile("cp.async.wait_group 1;" ::: "memory");
        } else {
            asm volatile("cp.async.wait_group 0;" ::: "memory");
        }
        __syncthreads();

        const float* As = Abuf[c & 1];
        const float* Bs = Bbuf[c & 1];
#pragma unroll
        for (int k8 = 0; k8 < 4; k8++) {
            const int kb = k8 * 8 + 2 * tig;
            uint32_t af[4][4], bf[4][2];
#pragma unroll
            for (int mt = 0; mt < 4; mt++) {
                load_afrag(af[mt], As + (wm * 64 + mt * 16 + gid) * GSTR + kb, GSTR);
                if (ROUND_A) {
                    af[mt][0] = rtf32u(af[mt][0]);
                    af[mt][1] = rtf32u(af[mt][1]);
                    af[mt][2] = rtf32u(af[mt][2]);
                    af[mt][3] = rtf32u(af[mt][3]);
                }
            }
#pragma unroll
            for (int nt = 0; nt < 4; nt++)
                load_bfrag(bf[nt], Bs + (wn * 32 + nt * 8 + gid) * GSTR + kb);
#pragma unroll
            for (int mt = 0; mt < 4; mt++)
#pragma unroll
                for (int nt = 0; nt < 4; nt++)
                    mma_tf32(acc[mt][nt], af[mt], bf[nt]);
        }
        __syncthreads();
    }

#pragma unroll
    for (int mt = 0; mt < 4; mt++) {
        int row = m0 + wm * 64 + mt * 16 + gid;
#pragma unroll
        for (int nt = 0; nt < 4; nt++) {
            int col = n0 + wn * 32 + nt * 8 + 2 * tig;
            float2 v0 = make_float2(acc[mt][nt][0], acc[mt][nt][1]);
            float2 v1 = make_float2(acc[mt][nt][2], acc[mt][nt][3]);
            if (BIAS) {
                float2 bb = *(const float2*)(bias + col);
                v0.x += bb.x; v0.y += bb.y;
                v1.x += bb.x; v1.y += bb.y;
            }
            if (ROUND_OUT) {
                v0.x = rtf32(v0.x); v0.y = rtf32(v0.y);
                v1.x = rtf32(v1.x); v1.y = rtf32(v1.y);
            }
            *(float2*)(C + (size_t)row * N + col) = v0;
            *(float2*)(C + (size_t)(row + 8) * N + col) = v1;
        }
    }
}

// ---------------------------------------------------------------------------
// Elementwise tf32 (RNA) rounding (weights only; tiny)
// ---------------------------------------------------------------------------
__global__ void round_tf32_k(const float4* __restrict__ in,
                             float4* __restrict__ out, int n4)
{
    int i = blockIdx.x * blockDim.x + threadIdx.x;
    if (i < n4) {
        float4 v = in[i];
        v.x = rtf32(v.x); v.y = rtf32(v.y);
        v.z = rtf32(v.z); v.w = rtf32(v.w);
        out[i] = v;
    }
}

// ---------------------------------------------------------------------------
// Tensor-core windowed attention. 256 CTAs (batch,window), 256 threads.
//   Phase A: S = Q.K2^T, warp grid 2x4 (64x64), k-pair LDS.64 frags, str 40.
//   Softmax into Ps (stride 264 = conflict-free LDS.64 phases).
//   Phase C: O = P.K2; 8 chunks of 64 d-cols, warp grid 4x2 (32x32 tiles).
// smem: Ps 128x264 + Kt 64x264 = 202752 B (phase-A staging overlays Ps).
// ---------------------------------------------------------------------------
#define ASTR 40
#define PSTR 264

__global__ __launch_bounds__(256, 1)
void attn_mma(const float* __restrict__ qk, float* __restrict__ ao)
{
    extern __shared__ float sm[];
    float* Ps = sm;                          // 128 x 264 = 33792 floats
    float* Kt = sm + 33792;                  // 64 x 264  = 16896 floats
    float* Qb[2] = {sm,         sm + 15360};
    float* Kb[2] = {sm + 5120,  sm + 20480};

    const int tid = threadIdx.x;
    const int wid = tid >> 5, lid = tid & 31;
    const int gid = lid >> 2, tig = lid & 3;
    const int b   = blockIdx.x >> 6;
    const int wi  = blockIdx.x & 63;
    const size_t qrow0 = (size_t)b * 8192 + (size_t)wi * 128;
    const bool w0 = (wi == 0);

    // ---- Phase A: S = Q . K2^T ----
    const int wm = wid >> 2, wn = wid & 3;   // 2x4 warp grid, 64x64 tiles
    float acc[4][8][4];
#pragma unroll
    for (int mt = 0; mt < 4; mt++)
#pragma unroll
        for (int nt = 0; nt < 8; nt++)
#pragma unroll
            for (int r = 0; r < 4; r++) acc[mt][nt][r] = 0.f;

    const float* Qg = qk + qrow0 * 1024;

    auto stage = [&](int c, int bi) {
        float* sQ = Qb[bi];
        float* sK = Kb[bi];
#pragma unroll
        for (int l = 0; l < 4; l++) {
            int idx = tid + l * 256;
            int row = idx >> 3, q = idx & 7;
            cpa16(smem_u32(sQ + row * ASTR + q * 4),
                  Qg + (size_t)row * 1024 + c * 32 + q * 4);
        }
#pragma unroll
        for (int l = 0; l < 8; l++) {
            int idx = tid + l * 256;
            int row = idx >> 3, q = idx & 7;
            const float* src = qk + (qrow0 + row - 128) * 1024 + 512 + c * 32 + q * 4;
            int sz = (w0 && row < 128) ? 0 : 16;
            cpa16z(smem_u32(sK + row * ASTR + q * 4), (w0 && row < 128) ? qk : src, sz);
        }
    };

    stage(0, 0);
    asm volatile("cp.async.commit_group;" ::: "memory");

    for (int c = 0; c < 16; c++) {
        if (c + 1 < 16) {
            stage(c + 1, (c + 1) & 1);
            asm volatile("cp.async.commit_group;" ::: "memory");
            asm volatile("cp.async.wait_group 1;" ::: "memory");
        } else {
            asm volatile("cp.async.wait_group 0;" ::: "memory");
        }
        __syncthreads();

        const float* sQ = Qb[c & 1];
        const float* sK = Kb[c & 1];
#pragma unroll
        for (int k8 = 0; k8 < 4; k8++) {
            const int kb = k8 * 8 + 2 * tig;
            uint32_t af[4][4], bf[8][2];
#pragma unroll
            for (int mt = 0; mt < 4; mt++)
                load_afrag(af[mt], sQ + (wm * 64 + mt * 16 + gid) * ASTR + kb, ASTR);
#pragma unroll
            for (int nt = 0; nt < 8; nt++)
                load_bfrag(bf[nt], sK + (wn * 64 + nt * 8 + gid) * ASTR + kb);
#pragma unroll
            for (int mt = 0; mt < 4; mt++)
#pragma unroll
                for (int nt = 0; nt < 8; nt++)
                    mma_tf32(acc[mt][nt], af[mt], bf[nt]);
        }
        __syncthreads();
    }

    // S -> Ps
#pragma unroll
    for (int mt = 0; mt < 4; mt++) {
        int row = wm * 64 + mt * 16 + gid;
#pragma unroll
        for (int nt = 0; nt < 8; nt++) {
            int col = wn * 64 + nt * 8 + 2 * tig;
            *(float2*)(Ps + row * PSTR + col) =
                make_float2(acc[mt][nt][0], acc[mt][nt][1]);
            *(float2*)(Ps + (row + 8) * PSTR + col) =
                make_float2(acc[mt][nt][2], acc[mt][nt][3]);
        }
    }
    __syncthreads();

    // ---- softmax ----
    {
        const float scale = 0.04419417382415922f;   // 512^-0.5
        const int tr = tid >> 4, tc = tid & 15;
#pragma unroll
        for (int ri = 0; ri < 8; ri++) {
            int i = tr * 8 + ri;
            float* prow = Ps + i * PSTR;
            float vv[16];
            float mx = -3.402823466e38f;
#pragma unroll
            for (int cj = 0; cj < 16; cj++) {
                int j = cj * 16 + tc;
                float v = prow[j] * scale;
                if (j > i + 128) v = -3.402823466e38f;
                vv[cj] = v;
                mx = fmaxf(mx, v);
            }
#pragma unroll
            for (int m = 8; m >= 1; m >>= 1)
                mx = fmaxf(mx, __shfl_xor_sync(0xffffffffu, mx, m));
            float sum = 0.f;
#pragma unroll
            for (int cj = 0; cj < 16; cj++) {
                vv[cj] = __expf(vv[cj] - mx);
                sum += vv[cj];
            }
#pragma unroll
            for (int m = 8; m >= 1; m >>= 1)
                sum += __shfl_xor_sync(0xffffffffu, sum, m);
            float inv = 1.f / sum;
#pragma unroll
            for (int cj = 0; cj < 16; cj++)
                prow[cj * 16 + tc] = rtf32(vv[cj] * inv);
        }
    }
    __syncthreads();

    // ---- Phase C: O = P . K2, 8 chunks of 64 d-cols ----
    const int wm2 = wid >> 1, wn2 = wid & 1;   // 4x2 warp grid, 32x32 tiles
    for (int co = 0; co < 8; co++) {
        int c0 = co * 64;
        // transpose-stage Kt[d][j]: thread tid owns j=row=tid; 16 float4 cols
#pragma unroll
        for (int l = 0; l < 16; l++) {
            float4 v = make_float4(0.f, 0.f, 0.f, 0.f);
            if (!(w0 && tid < 128))
                v = *(const float4*)(qk + (qrow0 + tid - 128) * 1024 + 512 + c0 + l * 4);
            Kt[(l * 4 + 0) * PSTR + tid] = v.x;
            Kt[(l * 4 + 1) * PSTR + tid] = v.y;
            Kt[(l * 4 + 2) * PSTR + tid] = v.z;
            Kt[(l * 4 + 3) * PSTR + tid] = v.w;
        }
        __syncthreads();

        float a2[2][4][4];
#pragma unroll
        for (int mt = 0; mt < 2; mt++)
#pragma unroll
            for (int nt = 0; nt < 4; nt++)
#pragma unroll
                for (int r = 0; r < 4; r++) a2[mt][nt][r] = 0.f;

#pragma unroll 4
        for (int k8 = 0; k8 < 32; k8++) {
            const int kb = k8 * 8 + 2 * tig;
            uint32_t af[2][4], bf[4][2];
#pragma unroll
            for (int mt = 0; mt < 2; mt++)
                load_afrag(af[mt], Ps + (wm2 * 32 + mt * 16 + gid) * PSTR + kb, PSTR);
#pragma unroll
            for (int nt = 0; nt < 4; nt++)
                load_bfrag(bf[nt], Kt + (wn2 * 32 + nt * 8 + gid) * PSTR + kb);
#pragma unroll
            for (int mt = 0; mt < 2; mt++)
#pragma unroll
                for (int nt = 0; nt < 4; nt++)
                    mma_tf32(a2[mt][nt], af[mt], bf[nt]);
        }

#pragma unroll
        for (int mt = 0; mt < 2; mt++) {
            size_t row = qrow0 + wm2 * 32 + mt * 16 + gid;
#pragma unroll
            for (int nt = 0; nt < 4; nt++) {
                int col = c0 + wn2 * 32 + nt * 8 + 2 * tig;
                *(float2*)(ao + row * 512 + col) =
                    make_float2(rtf32(a2[mt][nt][0]), rtf32(a2[mt][nt][1]));
                *(float2*)(ao + (row + 8) * 512 + col) =
                    make_float2(rtf32(a2[mt][nt][2]), rtf32(a2[mt][nt][3]));
            }
        }
        __syncthreads();
    }
}

// ---------------------------------------------------------------------------
extern "C" void kernel_launch(void* const* d_in, const int* in_sizes, int n_in,
                              void* d_out, int out_size)
{
    (void)in_sizes; (void)n_in; (void)out_size;
    const float* x     = (const float*)d_in[0];   // (4,8192,512)
    const float* w_qkv = (const float*)d_in[1];   // (1536,512); rows 0..1023 used
    const float* w_out = (const float*)d_in[2];   // (512,512)
    const float* b_out = (const float*)d_in[3];   // (512,)
    float* out = (float*)d_out;                   // (4,8192,512)

    float *qk, *ao, *wc, *wo;
    cudaGetSymbolAddress((void**)&qk, g_qk);
    cudaGetSymbolAddress((void**)&ao, g_ao);
    cudaGetSymbolAddress((void**)&wc, g_wc);
    cudaGetSymbolAddress((void**)&wo, g_wo);

    cudaFuncSetAttribute(attn_mma,
                         cudaFuncAttributeMaxDynamicSharedMemorySize, 202752);
    cudaFuncSetAttribute((const void*)mma_gemm<false, true, true>,
                         cudaFuncAttributeMaxDynamicSharedMemorySize, 81920);
    cudaFuncSetAttribute((const void*)mma_gemm<true, false, false>,
                         cudaFuncAttributeMaxDynamicSharedMemorySize, 81920);

    // 0) Round weights to tf32 (tiny; x is rounded in-register inside GEMM1).
    round_tf32_k<<<(131072 + 255) / 256, 256>>>((const float4*)w_qkv, (float4*)wc, 131072);
    round_tf32_k<<<(65536  + 255) / 256, 256>>>((const float4*)w_out, (float4*)wo, 65536);

    // 1) QK projection; A frags RNA-rounded in-register; output tf32-rounded.
    {
        dim3 g(1024 / 128, 32768 / 128);
        mma_gemm<false, true, true><<<g, 256, 81920>>>(x, wc, nullptr, qk, 1024, 512);
    }

    // 2) Tensor-core windowed attention (256 windows).
    attn_mma<<<256, 256, 202752>>>(qk, ao);

    // 3) Output projection + bias (A=g_ao already tf32-rounded).
    {
        dim3 g(512 / 128, 32768 / 128);
        mma_gemm<true, false, false><<<g, 256, 81920>>>(ao, wo, b_out, out, 512, 512);
    }
}

// round 11
// speedup vs baseline: 1.1535x; 1.0334x over previous
#include <cuda_runtime.h>
#include <math.h>
#include <stdint.h>

// ---------------------------------------------------------------------------
// Scratch (no cudaMalloc allowed)
// ---------------------------------------------------------------------------
__device__ float g_qk[33554432];   // 32768 x 1024  (Q | K) tf32-rounded
__device__ float g_ao[16777216];   // 32768 x 512   attention output (tf32-rounded)
__device__ float g_wc[524288];     // 1024 x 512    w_qkv rows 0..1023, tf32-rounded
__device__ float g_wo[262144];     // 512 x 512     w_out, tf32-rounded

__device__ __forceinline__ float rtf32(float v) {  // round-to-nearest tf32
    uint32_t r;
    asm("cvt.rna.tf32.f32 %0, %1;" : "=r"(r) : "f"(v));
    return __uint_as_float(r);
}
__device__ __forceinline__ uint32_t rtf32u(uint32_t v) {
    uint32_t r;
    asm("cvt.rna.tf32.f32 %0, %1;" : "=r"(r) : "f"(__uint_as_float(v)));
    return r;
}
__device__ __forceinline__ uint32_t smem_u32(const void* p) {
    uint32_t a;
    asm("{ .reg .u64 t; cvta.to.shared.u64 t, %1; cvt.u32.u64 %0, t; }"
        : "=r"(a) : "l"(p));
    return a;
}
__device__ __forceinline__ void cpa16(uint32_t s, const void* g) {
    asm volatile("cp.async.cg.shared.global [%0], [%1], 16;" :: "r"(s), "l"(g));
}
__device__ __forceinline__ void cpa16z(uint32_t s, const void* g, int sz) {
    asm volatile("cp.async.cg.shared.global [%0], [%1], 16, %2;"
                 :: "r"(s), "l"(g), "r"(sz));
}

// mma.sync m16n8k8 tf32. k within the k8 block is PERMUTED: thread tig owns
// k = {2*tig, 2*tig+1} (contiguous -> LDS.64 fragments). Valid because the
// same permutation is applied to both A and B (k-sum is order-invariant).
__device__ __forceinline__ void mma_tf32(float* d, const uint32_t* a,
                                         const uint32_t* b) {
    asm volatile(
        "mma.sync.aligned.m16n8k8.row.col.f32.tf32.tf32.f32 "
        "{%0,%1,%2,%3}, {%4,%5,%6,%7}, {%8,%9}, {%0,%1,%2,%3};"
        : "+f"(d[0]), "+f"(d[1]), "+f"(d[2]), "+f"(d[3])
        : "r"(a[0]), "r"(a[1]), "r"(a[2]), "r"(a[3]), "r"(b[0]), "r"(b[1]));
}

// Fragment loaders (k-pair permuted, LDS.64)
__device__ __forceinline__ void load_afrag(uint32_t* af, const float* ap,
                                           int str) {
    float2 p1 = *(const float2*)ap;            // (r,   k1),(r,   k2)
    float2 p2 = *(const float2*)(ap + 8 * str);// (r+8, k1),(r+8, k2)
    af[0] = __float_as_uint(p1.x);
    af[1] = __float_as_uint(p2.x);
    af[2] = __float_as_uint(p1.y);
    af[3] = __float_as_uint(p2.y);
}
__device__ __forceinline__ void load_bfrag(uint32_t* bf, const float* bp) {
    float2 q = *(const float2*)bp;             // (k1,n),(k2,n)
    bf[0] = __float_as_uint(q.x);
    bf[1] = __float_as_uint(q.y);
}

// ---------------------------------------------------------------------------
// tf32 mma.sync GEMM: C[M,N] = A[M,K] @ B[N,K]^T.
// CTA 128x128, 256 threads = 8 warps (2x4), warp tile 64x32.
// Tile stride 40 floats (160B == 32 mod 128 -> LDS.64 conflict-free).
// Dynamic smem: 4 * 128 * 40 * 4 = 81920 B (2 CTAs/SM).
// ---------------------------------------------------------------------------
#define GSTR 40

__device__ __forceinline__ void load_tile40(float* dst, const float* gsrc,
                                            int K, int tid) {
#pragma unroll
    for (int l = 0; l < 4; l++) {
        int idx = tid + l * 256;        // 0..1023 (128 rows x 8 x 16B)
        int row = idx >> 3;
        int q   = idx & 7;
        cpa16(smem_u32(dst + row * GSTR + q * 4),
              gsrc + (size_t)row * K + q * 4);
    }
}

template<bool BIAS, bool ROUND_OUT, bool ROUND_A>
__global__ __launch_bounds__(256, 2)
void mma_gemm(const float* __restrict__ A, const float* __restrict__ B,
              const float* __restrict__ bias, float* __restrict__ C,
              int N, int K)
{
    extern __shared__ float sm[];
    float* Abuf[2] = {sm,          sm + 5120};
    float* Bbuf[2] = {sm + 10240,  sm + 15360};

    const int tid = threadIdx.x;
    const int wid = tid >> 5, lid = tid & 31;
    const int gid = lid >> 2, tig = lid & 3;
    const int wm = wid >> 2, wn = wid & 3;       // 2x4 warp grid, 64x32 tiles
    const int n0 = blockIdx.x * 128, m0 = blockIdx.y * 128;
    const int NC = K >> 5;

    const float* gA = A + (size_t)m0 * K;
    const float* gB = B + (size_t)n0 * K;

    float acc[4][4][4];
#pragma unroll
    for (int mt = 0; mt < 4; mt++)
#pragma unroll
        for (int nt = 0; nt < 4; nt++)
#pragma unroll
            for (int r = 0; r < 4; r++) acc[mt][nt][r] = 0.f;

    load_tile40(Abuf[0], gA, K, tid);
    load_tile40(Bbuf[0], gB, K, tid);
    asm volatile("cp.async.commit_group;" ::: "memory");

    for (int c = 0; c < NC; c++) {
        if (c + 1 < NC) {
            int nb = (c + 1) & 1;
            load_tile40(Abuf[nb], gA + (c + 1) * 32, K, tid);
            load_tile40(Bbuf[nb], gB + (c + 1) * 32, K, tid);
            asm volatile("cp.async.commit_group;" ::: "memory");
            asm volatile("cp.async.wait_group 1;" ::: "memory");
        } else {
            asm volatile("cp.async.wait_group 0;" ::: "memory");
        }
        __syncthreads();

        const float* As = Abuf[c & 1];
        const float* Bs = Bbuf[c & 1];
#pragma unroll
        for (int k8 = 0; k8 < 4; k8++) {
            const int kb = k8 * 8 + 2 * tig;
            uint32_t af[4][4], bf[4][2];
#pragma unroll
            for (int mt = 0; mt < 4; mt++) {
                load_afrag(af[mt], As + (wm * 64 + mt * 16 + gid) * GSTR + kb, GSTR);
                if (ROUND_A) {
                    af[mt][0] = rtf32u(af[mt][0]);
                    af[mt][1] = rtf32u(af[mt][1]);
                    af[mt][2] = rtf32u(af[mt][2]);
                    af[mt][3] = rtf32u(af[mt][3]);
                }
            }
#pragma unroll
            for (int nt = 0; nt < 4; nt++)
                load_bfrag(bf[nt], Bs + (wn * 32 + nt * 8 + gid) * GSTR + kb);
#pragma unroll
            for (int mt = 0; mt < 4; mt++)
#pragma unroll
                for (int nt = 0; nt < 4; nt++)
                    mma_tf32(acc[mt][nt], af[mt], bf[nt]);
        }
        __syncthreads();
    }

#pragma unroll
    for (int mt = 0; mt < 4; mt++) {
        int row = m0 + wm * 64 + mt * 16 + gid;
#pragma unroll
        for (int nt = 0; nt < 4; nt++) {
            int col = n0 + wn * 32 + nt * 8 + 2 * tig;
            float2 v0 = make_float2(acc[mt][nt][0], acc[mt][nt][1]);
            float2 v1 = make_float2(acc[mt][nt][2], acc[mt][nt][3]);
            if (BIAS) {
                float2 bb = *(const float2*)(bias + col);
                v0.x += bb.x; v0.y += bb.y;
                v1.x += bb.x; v1.y += bb.y;
            }
            if (ROUND_OUT) {
                v0.x = rtf32(v0.x); v0.y = rtf32(v0.y);
                v1.x = rtf32(v1.x); v1.y = rtf32(v1.y);
            }
            *(float2*)(C + (size_t)row * N + col) = v0;
            *(float2*)(C + (size_t)(row + 8) * N + col) = v1;
        }
    }
}

// ---------------------------------------------------------------------------
// Elementwise tf32 (RNA) rounding (weights only; tiny)
// ---------------------------------------------------------------------------
__global__ void round_tf32_k(const float4* __restrict__ in,
                             float4* __restrict__ out, int n4)
{
    int i = blockIdx.x * blockDim.x + threadIdx.x;
    if (i < n4) {
        float4 v = in[i];
        v.x = rtf32(v.x); v.y = rtf32(v.y);
        v.z = rtf32(v.z); v.w = rtf32(v.w);
        out[i] = v;
    }
}

// ---------------------------------------------------------------------------
// Tensor-core windowed attention. 256 CTAs (batch,window), 256 threads.
//   Phase A: S = Q.K2^T, warp grid 2x4 (64x64), k-pair LDS.64 frags, str 40.
//   Softmax into Ps (stride 264), P written tf32-rounded.
//   Phase C: O = P.K2; NO transpose staging. K2 chunks (256 j x 32 d) staged
//     cp.async in NATURAL [j][d] layout, stride 36 (-> B-frag 2xLDS.32 hits
//     banks 8*tig+gid: all 32 distinct, conflict-free). Warp grid 4x2,
//     warp tile 32m x 16d. Chunk 0 prefetched before softmax.
// smem: Ps 128x264 + Kc 2x(256x36) = 208896 B.
// ---------------------------------------------------------------------------
#define ASTR 40
#define PSTR 264
#define CSTR 36

__global__ __launch_bounds__(256, 1)
void attn_mma(const float* __restrict__ qk, float* __restrict__ ao)
{
    extern __shared__ float sm[];
    float* Ps = sm;                          // 128 x 264 = 33792 floats
    float* Kc = sm + 33792;                  // 2 x 256 x 36 = 18432 floats
    float* Qb[2] = {sm,         sm + 15360};
    float* Kb[2] = {sm + 5120,  sm + 20480};

    const int tid = threadIdx.x;
    const int wid = tid >> 5, lid = tid & 31;
    const int gid = lid >> 2, tig = lid & 3;
    const int b   = blockIdx.x >> 6;
    const int wi  = blockIdx.x & 63;
    const size_t qrow0 = (size_t)b * 8192 + (size_t)wi * 128;
    const bool w0 = (wi == 0);

    // ---- Phase A: S = Q . K2^T ----
    const int wm = wid >> 2, wn = wid & 3;   // 2x4 warp grid, 64x64 tiles
    float acc[4][8][4];
#pragma unroll
    for (int mt = 0; mt < 4; mt++)
#pragma unroll
        for (int nt = 0; nt < 8; nt++)
#pragma unroll
            for (int r = 0; r < 4; r++) acc[mt][nt][r] = 0.f;

    const float* Qg = qk + qrow0 * 1024;

    auto stage = [&](int c, int bi) {
        float* sQ = Qb[bi];
        float* sK = Kb[bi];
#pragma unroll
        for (int l = 0; l < 4; l++) {
            int idx = tid + l * 256;
            int row = idx >> 3, q = idx & 7;
            cpa16(smem_u32(sQ + row * ASTR + q * 4),
                  Qg + (size_t)row * 1024 + c * 32 + q * 4);
        }
#pragma unroll
        for (int l = 0; l < 8; l++) {
            int idx = tid + l * 256;
            int row = idx >> 3, q = idx & 7;
            const float* src = qk + (qrow0 + row - 128) * 1024 + 512 + c * 32 + q * 4;
            int sz = (w0 && row < 128) ? 0 : 16;
            cpa16z(smem_u32(sK + row * ASTR + q * 4), (w0 && row < 128) ? qk : src, sz);
        }
    };

    // Phase-C chunk staging: natural layout [j][d], 32 d-cols, stride 36.
    auto stageC = [&](int c, int bi) {
        float* dst = Kc + bi * 9216;
#pragma unroll
        for (int l = 0; l < 8; l++) {
            int idx = tid + l * 256;        // 0..2047: 256 rows x 8 float4
            int row = idx >> 3, q = idx & 7;
            const float* src = qk + (qrow0 + row - 128) * 1024 + 512 + c * 32 + q * 4;
            int sz = (w0 && row < 128) ? 0 : 16;
            cpa16z(smem_u32(dst + row * CSTR + q * 4), (w0 && row < 128) ? qk : src, sz);
        }
    };

    stage(0, 0);
    asm volatile("cp.async.commit_group;" ::: "memory");

    for (int c = 0; c < 16; c++) {
        if (c + 1 < 16) {
            stage(c + 1, (c + 1) & 1);
            asm volatile("cp.async.commit_group;" ::: "memory");
            asm volatile("cp.async.wait_group 1;" ::: "memory");
        } else {
            asm volatile("cp.async.wait_group 0;" ::: "memory");
        }
        __syncthreads();

        const float* sQ = Qb[c & 1];
        const float* sK = Kb[c & 1];
#pragma unroll
        for (int k8 = 0; k8 < 4; k8++) {
            const int kb = k8 * 8 + 2 * tig;
            uint32_t af[4][4], bf[8][2];
#pragma unroll
            for (int mt = 0; mt < 4; mt++)
                load_afrag(af[mt], sQ + (wm * 64 + mt * 16 + gid) * ASTR + kb, ASTR);
#pragma unroll
            for (int nt = 0; nt < 8; nt++)
                load_bfrag(bf[nt], sK + (wn * 64 + nt * 8 + gid) * ASTR + kb);
#pragma unroll
            for (int mt = 0; mt < 4; mt++)
#pragma unroll
                for (int nt = 0; nt < 8; nt++)
                    mma_tf32(acc[mt][nt], af[mt], bf[nt]);
        }
        __syncthreads();
    }

    // Prefetch phase-C chunk 0 (Kc region is disjoint from Ps/softmax traffic;
    // overlaps the entire S->Ps + softmax section).
    stageC(0, 0);
    asm volatile("cp.async.commit_group;" ::: "memory");

    // S -> Ps
#pragma unroll
    for (int mt = 0; mt < 4; mt++) {
        int row = wm * 64 + mt * 16 + gid;
#pragma unroll
        for (int nt = 0; nt < 8; nt++) {
            int col = wn * 64 + nt * 8 + 2 * tig;
            *(float2*)(Ps + row * PSTR + col) =
                make_float2(acc[mt][nt][0], acc[mt][nt][1]);
            *(float2*)(Ps + (row + 8) * PSTR + col) =
                make_float2(acc[mt][nt][2], acc[mt][nt][3]);
        }
    }
    __syncthreads();

    // ---- softmax ----
    {
        const float scale = 0.04419417382415922f;   // 512^-0.5
        const int tr = tid >> 4, tc = tid & 15;
#pragma unroll
        for (int ri = 0; ri < 8; ri++) {
            int i = tr * 8 + ri;
            float* prow = Ps + i * PSTR;
            float vv[16];
            float mx = -3.402823466e38f;
#pragma unroll
            for (int cj = 0; cj < 16; cj++) {
                int j = cj * 16 + tc;
                float v = prow[j] * scale;
                if (j > i + 128) v = -3.402823466e38f;
                vv[cj] = v;
                mx = fmaxf(mx, v);
            }
#pragma unroll
            for (int m = 8; m >= 1; m >>= 1)
                mx = fmaxf(mx, __shfl_xor_sync(0xffffffffu, mx, m));
            float sum = 0.f;
#pragma unroll
            for (int cj = 0; cj < 16; cj++) {
                vv[cj] = __expf(vv[cj] - mx);
                sum += vv[cj];
            }
#pragma unroll
            for (int m = 8; m >= 1; m >>= 1)
                sum += __shfl_xor_sync(0xffffffffu, sum, m);
            float inv = 1.f / sum;
#pragma unroll
            for (int cj = 0; cj < 16; cj++)
                prow[cj * 16 + tc] = rtf32(vv[cj] * inv);
        }
    }
    __syncthreads();

    // ---- Phase C: O = P . K2, 16 chunks of 32 d-cols ----
    const int wm2 = wid >> 1, wn2 = wid & 1;   // 4x2 warp grid, 32x16 tiles
    for (int co = 0; co < 16; co++) {
        if (co + 1 < 16) {
            stageC(co + 1, (co + 1) & 1);
            asm volatile("cp.async.commit_group;" ::: "memory");
            asm volatile("cp.async.wait_group 1;" ::: "memory");
        } else {
            asm volatile("cp.async.wait_group 0;" ::: "memory");
        }
        __syncthreads();

        const float* Kb2 = Kc + (co & 1) * 9216;
        float a2[2][2][4];
#pragma unroll
        for (int mt = 0; mt < 2; mt++)
#pragma unroll
            for (int nt = 0; nt < 2; nt++)
#pragma unroll
                for (int r = 0; r < 4; r++) a2[mt][nt][r] = 0.f;

#pragma unroll 8
        for (int k8 = 0; k8 < 32; k8++) {
            const int kb = k8 * 8 + 2 * tig;
            uint32_t af[2][4], bf[2][2];
#pragma unroll
            for (int mt = 0; mt < 2; mt++)
                load_afrag(af[mt], Ps + (wm2 * 32 + mt * 16 + gid) * PSTR + kb, PSTR);
#pragma unroll
            for (int nt = 0; nt < 2; nt++) {
                const float* bp = Kb2 + kb * CSTR + wn2 * 16 + nt * 8 + gid;
                bf[nt][0] = __float_as_uint(bp[0]);
                bf[nt][1] = __float_as_uint(bp[CSTR]);
            }
#pragma unroll
            for (int mt = 0; mt < 2; mt++)
#pragma unroll
                for (int nt = 0; nt < 2; nt++)
                    mma_tf32(a2[mt][nt], af[mt], bf[nt]);
        }

        int c0 = co * 32;
#pragma unroll
        for (int mt = 0; mt < 2; mt++) {
            size_t row = qrow0 + wm2 * 32 + mt * 16 + gid;
#pragma unroll
            for (int nt = 0; nt < 2; nt++) {
                int col = c0 + wn2 * 16 + nt * 8 + 2 * tig;
                *(float2*)(ao + row * 512 + col) =
                    make_float2(rtf32(a2[mt][nt][0]), rtf32(a2[mt][nt][1]));
                *(float2*)(ao + (row + 8) * 512 + col) =
                    make_float2(rtf32(a2[mt][nt][2]), rtf32(a2[mt][nt][3]));
            }
        }
        __syncthreads();
    }
}

// ---------------------------------------------------------------------------
extern "C" void kernel_launch(void* const* d_in, const int* in_sizes, int n_in,
                              void* d_out, int out_size)
{
    (void)in_sizes; (void)n_in; (void)out_size;
    const float* x     = (const float*)d_in[0];   // (4,8192,512)
    const float* w_qkv = (const float*)d_in[1];   // (1536,512); rows 0..1023 used
    const float* w_out = (const float*)d_in[2];   // (512,512)
    const float* b_out = (const float*)d_in[3];   // (512,)
    float* out = (float*)d_out;                   // (4,8192,512)

    float *qk, *ao, *wc, *wo;
    cudaGetSymbolAddress((void**)&qk, g_qk);
    cudaGetSymbolAddress((void**)&ao, g_ao);
    cudaGetSymbolAddress((void**)&wc, g_wc);
    cudaGetSymbolAddress((void**)&wo, g_wo);

    cudaFuncSetAttribute(attn_mma,
                         cudaFuncAttributeMaxDynamicSharedMemorySize, 208896);
    cudaFuncSetAttribute((const void*)mma_gemm<false, true, true>,
                         cudaFuncAttributeMaxDynamicSharedMemorySize, 81920);
    cudaFuncSetAttribute((const void*)mma_gemm<true, false, false>,
                         cudaFuncAttributeMaxDynamicSharedMemorySize, 81920);

    // 0) Round weights to tf32 (tiny; x is rounded in-register inside GEMM1).
    round_tf32_k<<<(131072 + 255) / 256, 256>>>((const float4*)w_qkv, (float4*)wc, 131072);
    round_tf32_k<<<(65536  + 255) / 256, 256>>>((const float4*)w_out, (float4*)wo, 65536);

    // 1) QK projection; A frags RNA-rounded in-register; output tf32-rounded.
    {
        dim3 g(1024 / 128, 32768 / 128);
        mma_gemm<false, true, true><<<g, 256, 81920>>>(x, wc, nullptr, qk, 1024, 512);
    }

    // 2) Tensor-core windowed attention (256 windows).
    attn_mma<<<256, 256, 208896>>>(qk, ao);

    // 3) Output projection + bias (A=g_ao already tf32-rounded).
    {
        dim3 g(512 / 128, 32768 / 128);
        mma_gemm<true, false, false><<<g, 256, 81920>>>(ao, wo, b_out, out, 512, 512);
    }
}

// round 13
// speedup vs baseline: 1.1615x; 1.0070x over previous
#include <cuda_runtime.h>
#include <math.h>
#include <stdint.h>

// ---------------------------------------------------------------------------
// Scratch (no cudaMalloc allowed)
// ---------------------------------------------------------------------------
__device__ float g_qk[33554432];   // 32768 x 1024  (Q | K) tf32-rounded
__device__ float g_ao[16777216];   // 32768 x 512   attention output (tf32-rounded)
__device__ float g_wc[524288];     // 1024 x 512    w_qkv rows 0..1023, tf32-rounded
__device__ float g_wo[262144];     // 512 x 512     w_out, tf32-rounded

__device__ __forceinline__ float rtf32(float v) {  // round-to-nearest tf32
    uint32_t r;
    asm("cvt.rna.tf32.f32 %0, %1;" : "=r"(r) : "f"(v));
    return __uint_as_float(r);
}
__device__ __forceinline__ uint32_t rtf32u(uint32_t v) {
    uint32_t r;
    asm("cvt.rna.tf32.f32 %0, %1;" : "=r"(r) : "f"(__uint_as_float(v)));
    return r;
}
__device__ __forceinline__ uint32_t smem_u32(const void* p) {
    uint32_t a;
    asm("{ .reg .u64 t; cvta.to.shared.u64 t, %1; cvt.u32.u64 %0, t; }"
        : "=r"(a) : "l"(p));
    return a;
}
__device__ __forceinline__ void cpa16(uint32_t s, const void* g) {
    asm volatile("cp.async.cg.shared.global [%0], [%1], 16;" :: "r"(s), "l"(g));
}
__device__ __forceinline__ void cpa16z(uint32_t s, const void* g, int sz) {
    asm volatile("cp.async.cg.shared.global [%0], [%1], 16, %2;"
                 :: "r"(s), "l"(g), "r"(sz));
}

// mma.sync m16n8k8 tf32. k within the k8 block is PERMUTED: thread tig owns
// k = {2*tig, 2*tig+1} (contiguous -> LDS.64 fragments). Valid because the
// same permutation is applied to both A and B (k-sum is order-invariant).
__device__ __forceinline__ void mma_tf32(float* d, const uint32_t* a,
                                         const uint32_t* b) {
    asm volatile(
        "mma.sync.aligned.m16n8k8.row.col.f32.tf32.tf32.f32 "
        "{%0,%1,%2,%3}, {%4,%5,%6,%7}, {%8,%9}, {%0,%1,%2,%3};"
        : "+f"(d[0]), "+f"(d[1]), "+f"(d[2]), "+f"(d[3])
        : "r"(a[0]), "r"(a[1]), "r"(a[2]), "r"(a[3]), "r"(b[0]), "r"(b[1]));
}

// Fragment loaders (k-pair permuted, LDS.64)
__device__ __forceinline__ void load_afrag(uint32_t* af, const float* ap,
                                           int str) {
    float2 p1 = *(const float2*)ap;            // (r,   k1),(r,   k2)
    float2 p2 = *(const float2*)(ap + 8 * str);// (r+8, k1),(r+8, k2)
    af[0] = __float_as_uint(p1.x);
    af[1] = __float_as_uint(p2.x);
    af[2] = __float_as_uint(p1.y);
    af[3] = __float_as_uint(p2.y);
}
__device__ __forceinline__ void load_bfrag(uint32_t* bf, const float* bp) {
    float2 q = *(const float2*)bp;             // (k1,n),(k2,n)
    bf[0] = __float_as_uint(q.x);
    bf[1] = __float_as_uint(q.y);
}

// ---------------------------------------------------------------------------
// tf32 mma.sync GEMM: C[M,N] = A[M,K] @ B[N,K]^T.  (unchanged from R10)
// CTA 128x128, 256 threads = 8 warps (2x4), warp tile 64x32.
// ---------------------------------------------------------------------------
#define GSTR 40

__device__ __forceinline__ void load_tile40(float* dst, const float* gsrc,
                                            int K, int tid) {
#pragma unroll
    for (int l = 0; l < 4; l++) {
        int idx = tid + l * 256;        // 0..1023 (128 rows x 8 x 16B)
        int row = idx >> 3;
        int q   = idx & 7;
        cpa16(smem_u32(dst + row * GSTR + q * 4),
              gsrc + (size_t)row * K + q * 4);
    }
}

template<bool BIAS, bool ROUND_OUT, bool ROUND_A>
__global__ __launch_bounds__(256, 2)
void mma_gemm(const float* __restrict__ A, const float* __restrict__ B,
              const float* __restrict__ bias, float* __restrict__ C,
              int N, int K)
{
    extern __shared__ float sm[];
    float* Abuf[2] = {sm,          sm + 5120};
    float* Bbuf[2] = {sm + 10240,  sm + 15360};

    const int tid = threadIdx.x;
    const int wid = tid >> 5, lid = tid & 31;
    const int gid = lid >> 2, tig = lid & 3;
    const int wm = wid >> 2, wn = wid & 3;       // 2x4 warp grid, 64x32 tiles
    const int n0 = blockIdx.x * 128, m0 = blockIdx.y * 128;
    const int NC = K >> 5;

    const float* gA = A + (size_t)m0 * K;
    const float* gB = B + (size_t)n0 * K;

    float acc[4][4][4];
#pragma unroll
    for (int mt = 0; mt < 4; mt++)
#pragma unroll
        for (int nt = 0; nt < 4; nt++)
#pragma unroll
            for (int r = 0; r < 4; r++) acc[mt][nt][r] = 0.f;

    load_tile40(Abuf[0], gA, K, tid);
    load_tile40(Bbuf[0], gB, K, tid);
    asm volatile("cp.async.commit_group;" ::: "memory");

    for (int c = 0; c < NC; c++) {
        if (c + 1 < NC) {
            int nb = (c + 1) & 1;
            load_tile40(Abuf[nb], gA + (c + 1) * 32, K, tid);
            load_tile40(Bbuf[nb], gB + (c + 1) * 32, K, tid);
            asm volatile("cp.async.commit_group;" ::: "memory");
            asm volatile("cp.async.wait_group 1;" ::: "memory");
        } else {
            asm volatile("cp.async.wait_group 0;" ::: "memory");
        }
        __syncthreads();

        const float* As = Abuf[c & 1];
        const float* Bs = Bbuf[c & 1];
#pragma unroll
        for (int k8 = 0; k8 < 4; k8++) {
            const int kb = k8 * 8 + 2 * tig;
            uint32_t af[4][4], bf[4][2];
#pragma unroll
            for (int mt = 0; mt < 4; mt++) {
                load_afrag(af[mt], As + (wm * 64 + mt * 16 + gid) * GSTR + kb, GSTR);
                if (ROUND_A) {
                    af[mt][0] = rtf32u(af[mt][0]);
                    af[mt][1] = rtf32u(af[mt][1]);
                    af[mt][2] = rtf32u(af[mt][2]);
                    af[mt][3] = rtf32u(af[mt][3]);
                }
            }
#pragma unroll
            for (int nt = 0; nt < 4; nt++)
                load_bfrag(bf[nt], Bs + (wn * 32 + nt * 8 + gid) * GSTR + kb);
#pragma unroll
            for (int mt = 0; mt < 4; mt++)
#pragma unroll
                for (int nt = 0; nt < 4; nt++)
                    mma_tf32(acc[mt][nt], af[mt], bf[nt]);
        }
        __syncthreads();
    }

#pragma unroll
    for (int mt = 0; mt < 4; mt++) {
        int row = m0 + wm * 64 + mt * 16 + gid;
#pragma unroll
        for (int nt = 0; nt < 4; nt++) {
            int col = n0 + wn * 32 + nt * 8 + 2 * tig;
            float2 v0 = make_float2(acc[mt][nt][0], acc[mt][nt][1]);
            float2 v1 = make_float2(acc[mt][nt][2], acc[mt][nt][3]);
            if (BIAS) {
                float2 bb = *(const float2*)(bias + col);
                v0.x += bb.x; v0.y += bb.y;
                v1.x += bb.x; v1.y += bb.y;
            }
            if (ROUND_OUT) {
                v0.x = rtf32(v0.x); v0.y = rtf32(v0.y);
                v1.x = rtf32(v1.x); v1.y = rtf32(v1.y);
            }
            *(float2*)(C + (size_t)row * N + col) = v0;
            *(float2*)(C + (size_t)(row + 8) * N + col) = v1;
        }
    }
}

// ---------------------------------------------------------------------------
// Elementwise tf32 (RNA) rounding (weights only; tiny)
// ---------------------------------------------------------------------------
__global__ void round_tf32_k(const float4* __restrict__ in,
                             float4* __restrict__ out, int n4)
{
    int i = blockIdx.x * blockDim.x + threadIdx.x;
    if (i < n4) {
        float4 v = in[i];
        v.x = rtf32(v.x); v.y = rtf32(v.y);
        v.z = rtf32(v.z); v.w = rtf32(v.w);
        out[i] = v;
    }
}

// ---------------------------------------------------------------------------
// Tensor-core windowed attention. 256 CTAs (batch,window), 512 threads =
// 16 warps (4 per SMSP, vs 2 before).
//   Phase A: S = Q.K2^T, warp grid 4x4, warp tile 32x64, k-pair LDS.64 frags.
//   Softmax into Ps (stride 264), 32 row-groups x 4 rows.
//   Phase C: O = P.K2; 8 pairs of 32-d-col natural-layout buffers (stride 36),
//     warp grid 4x4 (32m x 16d tiles). Pair 0 prefetched before softmax.
// smem: Ps 128x264 + Kc 2x(256x36) = 208896 B.
// ---------------------------------------------------------------------------
#define ASTR 40
#define PSTR 264
#define CSTR 36

__global__ __launch_bounds__(512, 1)
void attn_mma(const float* __restrict__ qk, float* __restrict__ ao)
{
    extern __shared__ float sm[];
    float* Ps = sm;                          // 128 x 264 = 33792 floats
    float* Kc = sm + 33792;                  // 2 x 256 x 36 = 18432 floats
    float* Qb[2] = {sm,         sm + 15360};
    float* Kb[2] = {sm + 5120,  sm + 20480};

    const int tid = threadIdx.x;
    const int wid = tid >> 5, lid = tid & 31;
    const int gid = lid >> 2, tig = lid & 3;
    const int b   = blockIdx.x >> 6;
    const int wi  = blockIdx.x & 63;
    const size_t qrow0 = (size_t)b * 8192 + (size_t)wi * 128;
    const bool w0 = (wi == 0);

    // ---- Phase A: S = Q . K2^T ----
    const int wm = wid >> 2, wn = wid & 3;   // 4x4 warp grid, 32m x 64n tiles
    float acc[2][8][4];
#pragma unroll
    for (int mt = 0; mt < 2; mt++)
#pragma unroll
        for (int nt = 0; nt < 8; nt++)
#pragma unroll
            for (int r = 0; r < 4; r++) acc[mt][nt][r] = 0.f;

    const float* Qg = qk + qrow0 * 1024;

    auto stage = [&](int c, int bi) {
        float* sQ = Qb[bi];
        float* sK = Kb[bi];
#pragma unroll
        for (int l = 0; l < 2; l++) {
            int idx = tid + l * 512;        // 0..1023: 128 rows x 8 float4
            int row = idx >> 3, q = idx & 7;
            cpa16(smem_u32(sQ + row * ASTR + q * 4),
                  Qg + (size_t)row * 1024 + c * 32 + q * 4);
        }
#pragma unroll
        for (int l = 0; l < 4; l++) {
            int idx = tid + l * 512;        // 0..2047: 256 rows x 8 float4
            int row = idx >> 3, q = idx & 7;
            const float* src = qk + (qrow0 + row - 128) * 1024 + 512 + c * 32 + q * 4;
            int sz = (w0 && row < 128) ? 0 : 16;
            cpa16z(smem_u32(sK + row * ASTR + q * 4), (w0 && row < 128) ? qk : src, sz);
        }
    };

    // Phase-C pair staging: 64 d-cols into two 32-col buffers, natural [j][d].
    auto stageC2 = [&](int co2) {
#pragma unroll
        for (int l = 0; l < 8; l++) {
            int idx = tid + l * 512;        // 0..4095: 256 rows x 16 float4
            int row = idx >> 4;             // 0..255
            int q   = idx & 15;             // float4 index across 64 cols
            int buf = q >> 3, qq = q & 7;
            float* dst = Kc + buf * 9216 + row * CSTR + qq * 4;
            const float* src = qk + (qrow0 + row - 128) * 1024 + 512
                               + co2 * 64 + q * 4;
            int sz = (w0 && row < 128) ? 0 : 16;
            cpa16z(smem_u32(dst), (w0 && row < 128) ? qk : src, sz);
        }
    };

    stage(0, 0);
    asm volatile("cp.async.commit_group;" ::: "memory");

    for (int c = 0; c < 16; c++) {
        if (c + 1 < 16) {
            stage(c + 1, (c + 1) & 1);
            asm volatile("cp.async.commit_group;" ::: "memory");
            asm volatile("cp.async.wait_group 1;" ::: "memory");
        } else {
            asm volatile("cp.async.wait_group 0;" ::: "memory");
        }
        __syncthreads();

        const float* sQ = Qb[c & 1];
        const float* sK = Kb[c & 1];
#pragma unroll
        for (int k8 = 0; k8 < 4; k8++) {
            const int kb = k8 * 8 + 2 * tig;
            uint32_t af[2][4];
#pragma unroll
            for (int mt = 0; mt < 2; mt++)
                load_afrag(af[mt], sQ + (wm * 32 + mt * 16 + gid) * ASTR + kb, ASTR);
            // two nt-halves of 4 keep live B-frag regs low
#pragma unroll
            for (int h = 0; h < 2; h++) {
                uint32_t bf[4][2];
#pragma unroll
                for (int nt = 0; nt < 4; nt++)
                    load_bfrag(bf[nt],
                               sK + (wn * 64 + (h * 4 + nt) * 8 + gid) * ASTR + kb);
#pragma unroll
                for (int mt = 0; mt < 2; mt++)
#pragma unroll
                    for (int nt = 0; nt < 4; nt++)
                        mma_tf32(acc[mt][h * 4 + nt], af[mt], bf[nt]);
            }
        }
        __syncthreads();
    }

    // Prefetch phase-C pair 0 (Kc disjoint from Ps; overlaps S->Ps + softmax).
    stageC2(0);
    asm volatile("cp.async.commit_group;" ::: "memory");

    // S -> Ps
#pragma unroll
    for (int mt = 0; mt < 2; mt++) {
        int row = wm * 32 + mt * 16 + gid;
#pragma unroll
        for (int nt = 0; nt < 8; nt++) {
            int col = wn * 64 + nt * 8 + 2 * tig;
            *(float2*)(Ps + row * PSTR + col) =
                make_float2(acc[mt][nt][0], acc[mt][nt][1]);
            *(float2*)(Ps + (row + 8) * PSTR + col) =
                make_float2(acc[mt][nt][2], acc[mt][nt][3]);
        }
    }
    __syncthreads();

    // ---- softmax: 32 row-groups (tr) x 4 rows; cols j = cj*16 + tc ----
    {
        const float scale = 0.04419417382415922f;   // 512^-0.5
        const int tr = tid >> 4, tc = tid & 15;
#pragma unroll
        for (int ri = 0; ri < 4; ri++) {
            int i = tr * 4 + ri;
            float* prow = Ps + i * PSTR;
            float vv[16];
            float mx = -3.402823466e38f;
#pragma unroll
            for (int cj = 0; cj < 16; cj++) {
                int j = cj * 16 + tc;
                float v = prow[j] * scale;
                if (j > i + 128) v = -3.402823466e38f;
                vv[cj] = v;
                mx = fmaxf(mx, v);
            }
#pragma unroll
            for (int m = 8; m >= 1; m >>= 1)
                mx = fmaxf(mx, __shfl_xor_sync(0xffffffffu, mx, m));
            float sum = 0.f;
#pragma unroll
            for (int cj = 0; cj < 16; cj++) {
                vv[cj] = __expf(vv[cj] - mx);
                sum += vv[cj];
            }
#pragma unroll
            for (int m = 8; m >= 1; m >>= 1)
                sum += __shfl_xor_sync(0xffffffffu, sum, m);
            float inv = 1.f / sum;
#pragma unroll
            for (int cj = 0; cj < 16; cj++)
                prow[cj * 16 + tc] = rtf32(vv[cj] * inv);
        }
    }
    __syncthreads();

    // ---- Phase C: O = P . K2, 8 pairs of 64 d-cols; warp grid 4x4 ----
    const int wm2 = wid >> 2, wn2 = wid & 3;   // 32m x 16d warp tiles
    for (int co2 = 0; co2 < 8; co2++) {
        asm volatile("cp.async.wait_group 0;" ::: "memory");
        __syncthreads();

        const float* KbB = Kc + (wn2 >> 1) * 9216 + (wn2 & 1) * 16;
        float a2[2][2][4];
#pragma unroll
        for (int mt = 0; mt < 2; mt++)
#pragma unroll
            for (int nt = 0; nt < 2; nt++)
#pragma unroll
                for (int r = 0; r < 4; r++) a2[mt][nt][r] = 0.f;

#pragma unroll 8
        for (int k8 = 0; k8 < 32; k8++) {
            const int kb = k8 * 8 + 2 * tig;
            uint32_t af[2][4], bf[2][2];
#pragma unroll
            for (int mt = 0; mt < 2; mt++)
                load_afrag(af[mt], Ps + (wm2 * 32 + mt * 16 + gid) * PSTR + kb, PSTR);
#pragma unroll
            for (int nt = 0; nt < 2; nt++) {
                const float* bp = KbB + kb * CSTR + nt * 8 + gid;
                bf[nt][0] = __float_as_uint(bp[0]);
                bf[nt][1] = __float_as_uint(bp[CSTR]);
            }
#pragma unroll
            for (int mt = 0; mt < 2; mt++)
#pragma unroll
                for (int nt = 0; nt < 2; nt++)
                    mma_tf32(a2[mt][nt], af[mt], bf[nt]);
        }

        int c0 = co2 * 64;
#pragma unroll
        for (int mt = 0; mt < 2; mt++) {
            size_t row = qrow0 + wm2 * 32 + mt * 16 + gid;
#pragma unroll
            for (int nt = 0; nt < 2; nt++) {
                int col = c0 + wn2 * 16 + nt * 8 + 2 * tig;
                *(float2*)(ao + row * 512 + col) =
                    make_float2(rtf32(a2[mt][nt][0]), rtf32(a2[mt][nt][1]));
                *(float2*)(ao + (row + 8) * 512 + col) =
                    make_float2(rtf32(a2[mt][nt][2]), rtf32(a2[mt][nt][3]));
            }
        }
        __syncthreads();
        if (co2 + 1 < 8) {
            stageC2(co2 + 1);
            asm volatile("cp.async.commit_group;" ::: "memory");
        }
    }
}

// ---------------------------------------------------------------------------
extern "C" void kernel_launch(void* const* d_in, const int* in_sizes, int n_in,
                              void* d_out, int out_size)
{
    (void)in_sizes; (void)n_in; (void)out_size;
    const float* x     = (const float*)d_in[0];   // (4,8192,512)
    const float* w_qkv = (const float*)d_in[1];   // (1536,512); rows 0..1023 used
    const float* w_out = (const float*)d_in[2];   // (512,512)
    const float* b_out = (const float*)d_in[3];   // (512,)
    float* out = (float*)d_out;                   // (4,8192,512)

    float *qk, *ao, *wc, *wo;
    cudaGetSymbolAddress((void**)&qk, g_qk);
    cudaGetSymbolAddress((void**)&ao, g_ao);
    cudaGetSymbolAddress((void**)&wc, g_wc);
    cudaGetSymbolAddress((void**)&wo, g_wo);

    cudaFuncSetAttribute(attn_mma,
                         cudaFuncAttributeMaxDynamicSharedMemorySize, 208896);
    cudaFuncSetAttribute((const void*)mma_gemm<false, true, true>,
                         cudaFuncAttributeMaxDynamicSharedMemorySize, 81920);
    cudaFuncSetAttribute((const void*)mma_gemm<true, false, false>,
                         cudaFuncAttributeMaxDynamicSharedMemorySize, 81920);

    // 0) Round weights to tf32 (tiny; x is rounded in-register inside GEMM1).
    round_tf32_k<<<(131072 + 255) / 256, 256>>>((const float4*)w_qkv, (float4*)wc, 131072);
    round_tf32_k<<<(65536  + 255) / 256, 256>>>((const float4*)w_out, (float4*)wo, 65536);

    // 1) QK projection; A frags RNA-rounded in-register; output tf32-rounded.
    {
        dim3 g(1024 / 128, 32768 / 128);
        mma_gemm<false, true, true><<<g, 256, 81920>>>(x, wc, nullptr, qk, 1024, 512);
    }

    // 2) Tensor-core windowed attention (256 windows, 512 threads).
    attn_mma<<<256, 512, 208896>>>(qk, ao);

    // 3) Output projection + bias (A=g_ao already tf32-rounded).
    {
        dim3 g(512 / 128, 32768 / 128);
        mma_gemm<true, false, false><<<g, 256, 81920>>>(ao, wo, b_out, out, 512, 512);
    }
}

// round 14
// speedup vs baseline: 1.8829x; 1.6211x over previous
#include <cuda_runtime.h>
#include <cuda_fp16.h>
#include <math.h>
#include <stdint.h>

// ---------------------------------------------------------------------------
// Scratch (no cudaMalloc allowed)
// ---------------------------------------------------------------------------
__device__ __half g_qkh[33554432];  // 32768 x 1024 fp16 (Q | K)
__device__ __half g_aoh[16777216];  // 32768 x 512  fp16 attention output
__device__ __half g_xh[16777216];   // 32768 x 512  fp16 x
__device__ __half g_wh[524288];     // 1024 x 512   fp16 w_qkv rows 0..1023
__device__ __half g_woh[262144];    // 512 x 512    fp16 w_out

__device__ __forceinline__ uint32_t smem_u32(const void* p) {
    uint32_t a;
    asm("{ .reg .u64 t; cvta.to.shared.u64 t, %1; cvt.u32.u64 %0, t; }"
        : "=r"(a) : "l"(p));
    return a;
}
__device__ __forceinline__ void cpa16(uint32_t s, const void* g) {
    asm volatile("cp.async.cg.shared.global [%0], [%1], 16;" :: "r"(s), "l"(g));
}
__device__ __forceinline__ void cpa16z(uint32_t s, const void* g, int sz) {
    asm volatile("cp.async.cg.shared.global [%0], [%1], 16, %2;"
                 :: "r"(s), "l"(g), "r"(sz));
}

// mma.sync m16n8k16 fp16 (fp32 accum). k within the k16 block is PERMUTED:
// thread tig owns k = {4tig..4tig+3}; pairs (4tig,4tig+1) fill the "low k8"
// register slots and (4tig+2,4tig+3) the "high k8" slots, identically for A
// and B, so the contraction is a pure reordering (k-sum order-invariant).
__device__ __forceinline__ void mma_f16(float* d, const uint32_t* a,
                                        const uint32_t* b) {
    asm volatile(
        "mma.sync.aligned.m16n8k16.row.col.f32.f16.f16.f32 "
        "{%0,%1,%2,%3}, {%4,%5,%6,%7}, {%8,%9}, {%0,%1,%2,%3};"
        : "+f"(d[0]), "+f"(d[1]), "+f"(d[2]), "+f"(d[3])
        : "r"(a[0]), "r"(a[1]), "r"(a[2]), "r"(a[3]), "r"(b[0]), "r"(b[1]));
}

// A fragment: one LDS.64 per row (4 contiguous halves), rows r and r+8.
__device__ __forceinline__ void load_afrag16(uint32_t* af, const __half* ap,
                                             int str) {
    uint2 v1 = *(const uint2*)ap;            // row r:   (k0,k1),(k2,k3)
    uint2 v2 = *(const uint2*)(ap + 8 * str);// row r+8
    af[0] = v1.x; af[1] = v2.x; af[2] = v1.y; af[3] = v2.y;
}
// B fragment: one LDS.64 (4 contiguous halves along k).
__device__ __forceinline__ void load_bfrag16(uint32_t* bf, const __half* bp) {
    uint2 v = *(const uint2*)bp;
    bf[0] = v.x; bf[1] = v.y;
}
__device__ __forceinline__ uint32_t packh2(__half a, __half b) {
    __half2 h = __halves2half2(a, b);        // a -> low half
    return *reinterpret_cast<uint32_t*>(&h);
}

// ---------------------------------------------------------------------------
// fp16 mma GEMM: C[M,N] = A[M,K] @ B[N,K]^T.
// CTA 128x128, 256 threads = 8 warps (2x4), warp tile 64x32.
// K-chunks of 64 halves; tile stride 80 halves (160B: /8 == 4 mod 16 ->
// LDS.64 conflict-free). Smem: 4 * 128*80*2 = 81920 B (2 CTAs/SM).
// ---------------------------------------------------------------------------
#define HSTR 80

template<bool OUT_HALF, bool BIAS>
__global__ __launch_bounds__(256, 2)
void hgemm(const __half* __restrict__ A, const __half* __restrict__ B,
           const float* __restrict__ bias, void* __restrict__ Cv,
           int N, int K)
{
    extern __shared__ __half hm[];
    __half* Abuf[2] = {hm,          hm + 10240};
    __half* Bbuf[2] = {hm + 20480,  hm + 30720};

    const int tid = threadIdx.x;
    const int wid = tid >> 5, lid = tid & 31;
    const int gid = lid >> 2, tig = lid & 3;
    const int wm = wid >> 2, wn = wid & 3;       // 2x4 warp grid, 64x32 tiles
    const int n0 = blockIdx.x * 128, m0 = blockIdx.y * 128;
    const int NC = K >> 6;                       // chunks of 64 halves

    const __half* gA = A + (size_t)m0 * K;
    const __half* gB = B + (size_t)n0 * K;

    float acc[4][4][4];
#pragma unroll
    for (int mt = 0; mt < 4; mt++)
#pragma unroll
        for (int nt = 0; nt < 4; nt++)
#pragma unroll
            for (int r = 0; r < 4; r++) acc[mt][nt][r] = 0.f;

    auto load_tile = [&](__half* dst, const __half* gsrc, int c) {
#pragma unroll
        for (int l = 0; l < 4; l++) {
            int idx = tid + l * 256;        // 0..1023: 128 rows x 8 x 16B
            int row = idx >> 3, q = idx & 7;
            cpa16(smem_u32(dst + row * HSTR + q * 8),
                  gsrc + (size_t)row * K + c * 64 + q * 8);
        }
    };

    load_tile(Abuf[0], gA, 0);
    load_tile(Bbuf[0], gB, 0);
    asm volatile("cp.async.commit_group;" ::: "memory");

    for (int c = 0; c < NC; c++) {
        if (c + 1 < NC) {
            int nb = (c + 1) & 1;
            load_tile(Abuf[nb], gA, c + 1);
            load_tile(Bbuf[nb], gB, c + 1);
            asm volatile("cp.async.commit_group;" ::: "memory");
            asm volatile("cp.async.wait_group 1;" ::: "memory");
        } else {
            asm volatile("cp.async.wait_group 0;" ::: "memory");
        }
        __syncthreads();

        const __half* As = Abuf[c & 1];
        const __half* Bs = Bbuf[c & 1];
#pragma unroll
        for (int s = 0; s < 4; s++) {        // 4 k16 steps per 64-chunk
            const int kb = s * 16 + 4 * tig;
            uint32_t af[4][4], bf[4][2];
#pragma unroll
            for (int mt = 0; mt < 4; mt++)
                load_afrag16(af[mt], As + (wm * 64 + mt * 16 + gid) * HSTR + kb, HSTR);
#pragma unroll
            for (int nt = 0; nt < 4; nt++)
                load_bfrag16(bf[nt], Bs + (wn * 32 + nt * 8 + gid) * HSTR + kb);
#pragma unroll
            for (int mt = 0; mt < 4; mt++)
#pragma unroll
                for (int nt = 0; nt < 4; nt++)
                    mma_f16(acc[mt][nt], af[mt], bf[nt]);
        }
        __syncthreads();
    }

#pragma unroll
    for (int mt = 0; mt < 4; mt++) {
        int row = m0 + wm * 64 + mt * 16 + gid;
#pragma unroll
        for (int nt = 0; nt < 4; nt++) {
            int col = n0 + wn * 32 + nt * 8 + 2 * tig;
            if (OUT_HALF) {
                __half* C = (__half*)Cv;
                *(__half2*)(C + (size_t)row * N + col) =
                    __floats2half2_rn(acc[mt][nt][0], acc[mt][nt][1]);
                *(__half2*)(C + (size_t)(row + 8) * N + col) =
                    __floats2half2_rn(acc[mt][nt][2], acc[mt][nt][3]);
            } else {
                float* C = (float*)Cv;
                float2 v0 = make_float2(acc[mt][nt][0], acc[mt][nt][1]);
                float2 v1 = make_float2(acc[mt][nt][2], acc[mt][nt][3]);
                if (BIAS) {
                    float2 bb = *(const float2*)(bias + col);
                    v0.x += bb.x; v0.y += bb.y;
                    v1.x += bb.x; v1.y += bb.y;
                }
                *(float2*)(C + (size_t)row * N + col) = v0;
                *(float2*)(C + (size_t)(row + 8) * N + col) = v1;
            }
        }
    }
}

// ---------------------------------------------------------------------------
// Elementwise fp32 -> fp16 conversion
// ---------------------------------------------------------------------------
__global__ void f2h_k(const float4* __restrict__ in, uint2* __restrict__ out,
                      int n4)
{
    int i = blockIdx.x * blockDim.x + threadIdx.x;
    if (i < n4) {
        float4 v = in[i];
        uint2 o;
        __half2 h0 = __floats2half2_rn(v.x, v.y);
        __half2 h1 = __floats2half2_rn(v.z, v.w);
        o.x = *reinterpret_cast<uint32_t*>(&h0);
        o.y = *reinterpret_cast<uint32_t*>(&h1);
        out[i] = o;
    }
}

// ---------------------------------------------------------------------------
// fp16 tensor-core windowed attention. 256 CTAs (batch,window), 512 threads.
//   Phase A: S = Q.K2^T (fp16 in, fp32 acc), warp grid 4x4, tile 32m x 64n,
//            8 chunks of 64 d, double-buffered cp.async (stride 80 halves).
//   Softmax on fp32 S in Ps (stride 264 f32); P written fp16 IN PLACE over
//            each row's first 512 bytes (rows are half-warp-private;
//            __syncwarp between the fp32 reads and fp16 writes).
//   Phase C: O = P.K2 fp16; Kc staged natural [j][d] fp16 (stride 72 halves),
//            8 chunks of 64 d; warp grid 4x4 (32m x 16d); B-frags via 4
//            scalar LDS.16 + pack. Chunk 0 prefetched before softmax.
// smem: Ps 128*264*4 = 135168 B + Kc 2*256*72*2 = 73728 B = 208896 B.
// ---------------------------------------------------------------------------
#define ASTRH 80
#define PSTR  264
#define PSTRH 528
#define CSTRH 72

__global__ __launch_bounds__(512, 1)
void attn_mma(const __half* __restrict__ qk, __half* __restrict__ ao)
{
    extern __shared__ float sm[];
    float*  Ps = sm;                         // 128 x 264 f32
    __half* hmem = (__half*)sm;
    __half* Qb[2] = {hmem,          hmem + 10240};
    __half* Kb[2] = {hmem + 20480,  hmem + 40960};
    __half* Kc = (__half*)(sm + 33792);      // 2 x 256 x 72 halves

    const int tid = threadIdx.x;
    const int wid = tid >> 5, lid = tid & 31;
    const int gid = lid >> 2, tig = lid & 3;
    const int b   = blockIdx.x >> 6;
    const int wi  = blockIdx.x & 63;
    const size_t qrow0 = (size_t)b * 8192 + (size_t)wi * 128;
    const bool w0 = (wi == 0);

    // ---- Phase A: S = Q . K2^T ----
    const int wm = wid >> 2, wn = wid & 3;   // 4x4 warp grid, 32m x 64n tiles
    float acc[2][8][4];
#pragma unroll
    for (int mt = 0; mt < 2; mt++)
#pragma unroll
        for (int nt = 0; nt < 8; nt++)
#pragma unroll
            for (int r = 0; r < 4; r++) acc[mt][nt][r] = 0.f;

    const __half* Qg = qk + qrow0 * 1024;

    auto stage = [&](int c, int bi) {
        __half* sQ = Qb[bi];
        __half* sK = Kb[bi];
#pragma unroll
        for (int l = 0; l < 2; l++) {
            int idx = tid + l * 512;        // 0..1023: 128 rows x 8 x 16B
            int row = idx >> 3, q = idx & 7;
            cpa16(smem_u32(sQ + row * ASTRH + q * 8),
                  Qg + (size_t)row * 1024 + c * 64 + q * 8);
        }
#pragma unroll
        for (int l = 0; l < 4; l++) {
            int idx = tid + l * 512;        // 0..2047: 256 rows x 8 x 16B
            int row = idx >> 3, q = idx & 7;
            const __half* src = qk + (qrow0 + row - 128) * 1024 + 512 + c * 64 + q * 8;
            int sz = (w0 && row < 128) ? 0 : 16;
            cpa16z(smem_u32(sK + row * ASTRH + q * 8), (w0 && row < 128) ? qk : src, sz);
        }
    };

    // Phase-C chunk staging: natural [j][d] fp16, 64 d-cols, stride 72 halves.
    auto stageC = [&](int c, int bi) {
        __half* dst = Kc + bi * 18432;
#pragma unroll
        for (int l = 0; l < 4; l++) {
            int idx = tid + l * 512;        // 0..2047: 256 rows x 8 x 16B
            int row = idx >> 3, q = idx & 7;
            const __half* src = qk + (qrow0 + row - 128) * 1024 + 512 + c * 64 + q * 8;
            int sz = (w0 && row < 128) ? 0 : 16;
            cpa16z(smem_u32(dst + row * CSTRH + q * 8), (w0 && row < 128) ? qk : src, sz);
        }
    };

    stage(0, 0);
    asm volatile("cp.async.commit_group;" ::: "memory");

    for (int c = 0; c < 8; c++) {
        if (c + 1 < 8) {
            stage(c + 1, (c + 1) & 1);
            asm volatile("cp.async.commit_group;" ::: "memory");
            asm volatile("cp.async.wait_group 1;" ::: "memory");
        } else {
            asm volatile("cp.async.wait_group 0;" ::: "memory");
        }
        __syncthreads();

        const __half* sQ = Qb[c & 1];
        const __half* sK = Kb[c & 1];
#pragma unroll
        for (int s = 0; s < 4; s++) {        // 4 k16 per 64-d chunk
            const int kb = s * 16 + 4 * tig;
            uint32_t af[2][4];
#pragma unroll
            for (int mt = 0; mt < 2; mt++)
                load_afrag16(af[mt], sQ + (wm * 32 + mt * 16 + gid) * ASTRH + kb, ASTRH);
#pragma unroll
            for (int h = 0; h < 2; h++) {
                uint32_t bf[4][2];
#pragma unroll
                for (int nt = 0; nt < 4; nt++)
                    load_bfrag16(bf[nt],
                                 sK + (wn * 64 + (h * 4 + nt) * 8 + gid) * ASTRH + kb);
#pragma unroll
                for (int mt = 0; mt < 2; mt++)
#pragma unroll
                    for (int nt = 0; nt < 4; nt++)
                        mma_f16(acc[mt][h * 4 + nt], af[mt], bf[nt]);
            }
        }
        __syncthreads();
    }

    // Prefetch phase-C chunk 0 (Kc disjoint from Ps; overlaps S->Ps + softmax).
    stageC(0, 0);
    asm volatile("cp.async.commit_group;" ::: "memory");

    // S -> Ps (fp32)
#pragma unroll
    for (int mt = 0; mt < 2; mt++) {
        int row = wm * 32 + mt * 16 + gid;
#pragma unroll
        for (int nt = 0; nt < 8; nt++) {
            int col = wn * 64 + nt * 8 + 2 * tig;
            *(float2*)(Ps + row * PSTR + col) =
                make_float2(acc[mt][nt][0], acc[mt][nt][1]);
            *(float2*)(Ps + (row + 8) * PSTR + col) =
                make_float2(acc[mt][nt][2], acc[mt][nt][3]);
        }
    }
    __syncthreads();

    // ---- softmax: 32 row-groups (tr) x 4 rows; cols j = cj*16 + tc ----
    // P written back fp16 IN PLACE over the row (rows are half-warp-private).
    {
        const float scale = 0.04419417382415922f;   // 512^-0.5
        const int tr = tid >> 4, tc = tid & 15;
#pragma unroll
        for (int ri = 0; ri < 4; ri++) {
            int i = tr * 4 + ri;
            float* prow = Ps + i * PSTR;
            float vv[16];
            float mx = -3.402823466e38f;
#pragma unroll
            for (int cj = 0; cj < 16; cj++) {
                int j = cj * 16 + tc;
                float v = prow[j] * scale;
                if (j > i + 128) v = -3.402823466e38f;
                vv[cj] = v;
                mx = fmaxf(mx, v);
            }
#pragma unroll
            for (int m = 8; m >= 1; m >>= 1)
                mx = fmaxf(mx, __shfl_xor_sync(0xffffffffu, mx, m));
            float sum = 0.f;
#pragma unroll
            for (int cj = 0; cj < 16; cj++) {
                vv[cj] = __expf(vv[cj] - mx);
                sum += vv[cj];
            }
#pragma unroll
            for (int m = 8; m >= 1; m >>= 1)
                sum += __shfl_xor_sync(0xffffffffu, sum, m);
            float inv = 1.f / sum;
            __syncwarp();                    // all fp32 reads done before fp16 writes
            __half* ph = (__half*)prow;
#pragma unroll
            for (int cj = 0; cj < 16; cj++)
                ph[cj * 16 + tc] = __float2half_rn(vv[cj] * inv);
        }
    }
    __syncthreads();

    // ---- Phase C: O = P . K2 (fp16), 8 chunks of 64 d-cols; warp grid 4x4 ----
    const int wm2 = wid >> 2, wn2 = wid & 3;   // 32m x 16d warp tiles
    const __half* Ph = (const __half*)Ps;
    for (int co = 0; co < 8; co++) {
        if (co + 1 < 8) {
            stageC(co + 1, (co + 1) & 1);
            asm volatile("cp.async.commit_group;" ::: "memory");
            asm volatile("cp.async.wait_group 1;" ::: "memory");
        } else {
            asm volatile("cp.async.wait_group 0;" ::: "memory");
        }
        __syncthreads();

        const __half* Kcb = Kc + (co & 1) * 18432;
        float a2[2][2][4];
#pragma unroll
        for (int mt = 0; mt < 2; mt++)
#pragma unroll
            for (int nt = 0; nt < 2; nt++)
#pragma unroll
                for (int r = 0; r < 4; r++) a2[mt][nt][r] = 0.f;

#pragma unroll 4
        for (int k16 = 0; k16 < 16; k16++) {
            const int kb = k16 * 16 + 4 * tig;
            uint32_t af[2][4], bf[2][2];
#pragma unroll
            for (int mt = 0; mt < 2; mt++)
                load_afrag16(af[mt], Ph + (wm2 * 32 + mt * 16 + gid) * PSTRH + kb, PSTRH);
#pragma unroll
            for (int nt = 0; nt < 2; nt++) {
                const __half* bp = Kcb + kb * CSTRH + wn2 * 16 + nt * 8 + gid;
                bf[nt][0] = packh2(bp[0],         bp[CSTRH]);
                bf[nt][1] = packh2(bp[2 * CSTRH], bp[3 * CSTRH]);
            }
#pragma unroll
            for (int mt = 0; mt < 2; mt++)
#pragma unroll
                for (int nt = 0; nt < 2; nt++)
                    mma_f16(a2[mt][nt], af[mt], bf[nt]);
        }

        int c0 = co * 64;
#pragma unroll
        for (int mt = 0; mt < 2; mt++) {
            size_t row = qrow0 + wm2 * 32 + mt * 16 + gid;
#pragma unroll
            for (int nt = 0; nt < 2; nt++) {
                int col = c0 + wn2 * 16 + nt * 8 + 2 * tig;
                *(__half2*)(ao + row * 512 + col) =
                    __floats2half2_rn(a2[mt][nt][0], a2[mt][nt][1]);
                *(__half2*)(ao + (row + 8) * 512 + col) =
                    __floats2half2_rn(a2[mt][nt][2], a2[mt][nt][3]);
            }
        }
        __syncthreads();
    }
}

// ---------------------------------------------------------------------------
extern "C" void kernel_launch(void* const* d_in, const int* in_sizes, int n_in,
                              void* d_out, int out_size)
{
    (void)in_sizes; (void)n_in; (void)out_size;
    const float* x     = (const float*)d_in[0];   // (4,8192,512)
    const float* w_qkv = (const float*)d_in[1];   // (1536,512); rows 0..1023 used
    const float* w_out = (const float*)d_in[2];   // (512,512)
    const float* b_out = (const float*)d_in[3];   // (512,)
    float* out = (float*)d_out;                   // (4,8192,512)

    __half *qkh, *aoh, *xh, *wh, *woh;
    cudaGetSymbolAddress((void**)&qkh, g_qkh);
    cudaGetSymbolAddress((void**)&aoh, g_aoh);
    cudaGetSymbolAddress((void**)&xh,  g_xh);
    cudaGetSymbolAddress((void**)&wh,  g_wh);
    cudaGetSymbolAddress((void**)&woh, g_woh);

    cudaFuncSetAttribute(attn_mma,
                         cudaFuncAttributeMaxDynamicSharedMemorySize, 208896);
    cudaFuncSetAttribute((const void*)hgemm<true, false>,
                         cudaFuncAttributeMaxDynamicSharedMemorySize, 81920);
    cudaFuncSetAttribute((const void*)hgemm<false, true>,
                         cudaFuncAttributeMaxDynamicSharedMemorySize, 81920);

    // 0) Convert operands to fp16 (same 10-bit mantissa as tf32).
    f2h_k<<<(4194304 + 255) / 256, 256>>>((const float4*)x, (uint2*)xh, 4194304);
    f2h_k<<<(131072  + 255) / 256, 256>>>((const float4*)w_qkv, (uint2*)wh, 131072);
    f2h_k<<<(65536   + 255) / 256, 256>>>((const float4*)w_out, (uint2*)woh, 65536);

    // 1) QK projection (fp16 in, fp16 out). V is dead in the reference.
    {
        dim3 g(1024 / 128, 32768 / 128);
        hgemm<true, false><<<g, 256, 81920>>>(xh, wh, nullptr, qkh, 1024, 512);
    }

    // 2) fp16 tensor-core windowed attention (256 windows, 512 threads).
    attn_mma<<<256, 512, 208896>>>(qkh, aoh);

    // 3) Output projection + bias (fp16 in, fp32 out).
    {
        dim3 g(512 / 128, 32768 / 128);
        hgemm<false, true><<<g, 256, 81920>>>(aoh, woh, b_out, out, 512, 512);
    }
}

// round 15
// speedup vs baseline: 2.0286x; 1.0773x over previous
#include <cuda_runtime.h>
#include <cuda_fp16.h>
#include <math.h>
#include <stdint.h>

// ---------------------------------------------------------------------------
// Scratch (no cudaMalloc allowed)
// ---------------------------------------------------------------------------
__device__ __half g_qkh[33554432];  // 32768 x 1024 fp16 (Q | K)
__device__ __half g_aoh[16777216];  // 32768 x 512  fp16 attention output
__device__ __half g_xh[16777216];   // 32768 x 512  fp16 x
__device__ __half g_wh[524288];     // 1024 x 512   fp16 w_qkv rows 0..1023
__device__ __half g_woh[262144];    // 512 x 512    fp16 w_out

__device__ __forceinline__ uint32_t smem_u32(const void* p) {
    uint32_t a;
    asm("{ .reg .u64 t; cvta.to.shared.u64 t, %1; cvt.u32.u64 %0, t; }"
        : "=r"(a) : "l"(p));
    return a;
}
__device__ __forceinline__ void cpa16(uint32_t s, const void* g) {
    asm volatile("cp.async.cg.shared.global [%0], [%1], 16;" :: "r"(s), "l"(g));
}
__device__ __forceinline__ void cpa16z(uint32_t s, const void* g, int sz) {
    asm volatile("cp.async.cg.shared.global [%0], [%1], 16, %2;"
                 :: "r"(s), "l"(g), "r"(sz));
}

// mma.sync m16n8k16 fp16 (fp32 accum), canonical fragment layout (LDSM-fed).
__device__ __forceinline__ void mma_f16(float* d, const uint32_t* a,
                                        const uint32_t* b) {
    asm volatile(
        "mma.sync.aligned.m16n8k16.row.col.f32.f16.f16.f32 "
        "{%0,%1,%2,%3}, {%4,%5,%6,%7}, {%8,%9}, {%0,%1,%2,%3};"
        : "+f"(d[0]), "+f"(d[1]), "+f"(d[2]), "+f"(d[3])
        : "r"(a[0]), "r"(a[1]), "r"(a[2]), "r"(a[3]), "r"(b[0]), "r"(b[1]));
}

__device__ __forceinline__ void ldsm_x4(uint32_t* r, uint32_t addr) {
    asm volatile("ldmatrix.sync.aligned.m8n8.x4.shared.b16 {%0,%1,%2,%3}, [%4];"
                 : "=r"(r[0]), "=r"(r[1]), "=r"(r[2]), "=r"(r[3]) : "r"(addr));
}
__device__ __forceinline__ void ldsm_x2t(uint32_t* r, uint32_t addr) {
    asm volatile("ldmatrix.sync.aligned.m8n8.x2.trans.shared.b16 {%0,%1}, [%2];"
                 : "=r"(r[0]), "=r"(r[1]) : "r"(addr));
}

// ---------------------------------------------------------------------------
// fp16 mma GEMM: C[M,N] = A[M,K] @ B[N,K]^T.
// CTA 128x128, 256 threads = 8 warps (2x4), warp tile 64x32. LDSM fragments.
// Tile stride 72 halves (144B == 16 mod 128 -> LDSM conflict-free; STS
// 4-phase optimal). Smem: 4 * 128*72*2 = 73728 B (2 CTAs/SM).
// ---------------------------------------------------------------------------
#define HSTR 72

template<bool OUT_HALF, bool BIAS>
__global__ __launch_bounds__(256, 2)
void hgemm(const __half* __restrict__ A, const __half* __restrict__ B,
           const float* __restrict__ bias, void* __restrict__ Cv,
           int N, int K)
{
    extern __shared__ __half hm[];
    __half* Abuf[2] = {hm,          hm + 9216};
    __half* Bbuf[2] = {hm + 18432,  hm + 27648};

    const int tid = threadIdx.x;
    const int wid = tid >> 5, lid = tid & 31;
    const int gid = lid >> 2, tig = lid & 3;
    const int wm = wid >> 2, wn = wid & 3;       // 2x4 warp grid, 64x32 tiles
    const int n0 = blockIdx.x * 128, m0 = blockIdx.y * 128;
    const int NC = K >> 6;                       // chunks of 64 halves

    // LDSM per-lane offsets
    const int aRow = (lid & 7) + ((lid >> 3) & 1) * 8;   // A x4: row in 16
    const int aKof = (lid >> 4) * 8;                     // A x4: k 0/8
    const int bRow = (lid & 7) + ((lid >> 4) & 1) * 8;   // B x4: n in 16
    const int bKof = ((lid >> 3) & 1) * 8;               // B x4: k 0/8

    const __half* gA = A + (size_t)m0 * K;
    const __half* gB = B + (size_t)n0 * K;

    float acc[4][4][4];
#pragma unroll
    for (int mt = 0; mt < 4; mt++)
#pragma unroll
        for (int nt = 0; nt < 4; nt++)
#pragma unroll
            for (int r = 0; r < 4; r++) acc[mt][nt][r] = 0.f;

    auto load_tile = [&](__half* dst, const __half* gsrc, int c) {
#pragma unroll
        for (int l = 0; l < 4; l++) {
            int idx = tid + l * 256;        // 0..1023: 128 rows x 8 x 16B
            int row = idx >> 3, q = idx & 7;
            cpa16(smem_u32(dst + row * HSTR + q * 8),
                  gsrc + (size_t)row * K + c * 64 + q * 8);
        }
    };

    load_tile(Abuf[0], gA, 0);
    load_tile(Bbuf[0], gB, 0);
    asm volatile("cp.async.commit_group;" ::: "memory");

    for (int c = 0; c < NC; c++) {
        if (c + 1 < NC) {
            int nb = (c + 1) & 1;
            load_tile(Abuf[nb], gA, c + 1);
            load_tile(Bbuf[nb], gB, c + 1);
            asm volatile("cp.async.commit_group;" ::: "memory");
            asm volatile("cp.async.wait_group 1;" ::: "memory");
        } else {
            asm volatile("cp.async.wait_group 0;" ::: "memory");
        }
        __syncthreads();

        const __half* As = Abuf[c & 1];
        const __half* Bs = Bbuf[c & 1];
#pragma unroll
        for (int s = 0; s < 4; s++) {        // 4 k16 steps per 64-chunk
            const int kb = s * 16;
            uint32_t af[4][4], bf[4][2];
#pragma unroll
            for (int mt = 0; mt < 4; mt++)
                ldsm_x4(af[mt], smem_u32(As + (wm * 64 + mt * 16 + aRow) * HSTR
                                            + kb + aKof));
#pragma unroll
            for (int np = 0; np < 2; np++) {
                uint32_t r4[4];
                ldsm_x4(r4, smem_u32(Bs + (wn * 32 + np * 16 + bRow) * HSTR
                                        + kb + bKof));
                bf[np * 2 + 0][0] = r4[0]; bf[np * 2 + 0][1] = r4[1];
                bf[np * 2 + 1][0] = r4[2]; bf[np * 2 + 1][1] = r4[3];
            }
#pragma unroll
            for (int mt = 0; mt < 4; mt++)
#pragma unroll
                for (int nt = 0; nt < 4; nt++)
                    mma_f16(acc[mt][nt], af[mt], bf[nt]);
        }
        __syncthreads();
    }

#pragma unroll
    for (int mt = 0; mt < 4; mt++) {
        int row = m0 + wm * 64 + mt * 16 + gid;
#pragma unroll
        for (int nt = 0; nt < 4; nt++) {
            int col = n0 + wn * 32 + nt * 8 + 2 * tig;
            if (OUT_HALF) {
                __half* C = (__half*)Cv;
                *(__half2*)(C + (size_t)row * N + col) =
                    __floats2half2_rn(acc[mt][nt][0], acc[mt][nt][1]);
                *(__half2*)(C + (size_t)(row + 8) * N + col) =
                    __floats2half2_rn(acc[mt][nt][2], acc[mt][nt][3]);
            } else {
                float* C = (float*)Cv;
                float2 v0 = make_float2(acc[mt][nt][0], acc[mt][nt][1]);
                float2 v1 = make_float2(acc[mt][nt][2], acc[mt][nt][3]);
                if (BIAS) {
                    float2 bb = *(const float2*)(bias + col);
                    v0.x += bb.x; v0.y += bb.y;
                    v1.x += bb.x; v1.y += bb.y;
                }
                *(float2*)(C + (size_t)row * N + col) = v0;
                *(float2*)(C + (size_t)(row + 8) * N + col) = v1;
            }
        }
    }
}

// ---------------------------------------------------------------------------
// Elementwise fp32 -> fp16 conversion
// ---------------------------------------------------------------------------
__global__ void f2h_k(const float4* __restrict__ in, uint2* __restrict__ out,
                      int n4)
{
    int i = blockIdx.x * blockDim.x + threadIdx.x;
    if (i < n4) {
        float4 v = in[i];
        uint2 o;
        __half2 h0 = __floats2half2_rn(v.x, v.y);
        __half2 h1 = __floats2half2_rn(v.z, v.w);
        o.x = *reinterpret_cast<uint32_t*>(&h0);
        o.y = *reinterpret_cast<uint32_t*>(&h1);
        out[i] = o;
    }
}

// ---------------------------------------------------------------------------
// fp16 tensor-core windowed attention (LDSM fragments). 256 CTAs, 512 thr.
//   Phase A: S = Q.K2^T, warp grid 4x4, tile 32m x 64n; A/B via ldmatrix.x4.
//   Softmax on fp32 S in Ps (stride 260 f32 = 1040B == 16 mod 128); P fp16
//            in place over each row (rows half-warp-private; __syncwarp).
//   Phase C: O = P.K2; Kc natural [j][d] fp16 (stride 72), A via ldmatrix.x4
//            from Ph, B via ldmatrix.x2.trans. 8 chunks of 64 d.
// smem: Ps 128*260*4 = 133120 B + Kc 2*256*72*2 = 73728 B = 206848 B.
// ---------------------------------------------------------------------------
#define ASTRH 72
#define PSTR  260
#define PSTRH 520
#define CSTRH 72

__global__ __launch_bounds__(512, 1)
void attn_mma(const __half* __restrict__ qk, __half* __restrict__ ao)
{
    extern __shared__ float sm[];
    float*  Ps = sm;                         // 128 x 260 f32
    __half* hmem = (__half*)sm;
    __half* Qb[2] = {hmem,          hmem + 9216};
    __half* Kb[2] = {hmem + 18432,  hmem + 36864};
    __half* Kc = (__half*)(sm + 33280);      // 2 x 256 x 72 halves

    const int tid = threadIdx.x;
    const int wid = tid >> 5, lid = tid & 31;
    const int gid = lid >> 2, tig = lid & 3;
    const int b   = blockIdx.x >> 6;
    const int wi  = blockIdx.x & 63;
    const size_t qrow0 = (size_t)b * 8192 + (size_t)wi * 128;
    const bool w0 = (wi == 0);

    // LDSM per-lane offsets
    const int aRow = (lid & 7) + ((lid >> 3) & 1) * 8;
    const int aKof = (lid >> 4) * 8;
    const int bRow = (lid & 7) + ((lid >> 4) & 1) * 8;
    const int bKof = ((lid >> 3) & 1) * 8;
    const int tRow = (lid & 7) + ((lid >> 3) & 1) * 8;   // x2.trans j-offset
                                                          // (lanes 16-31 dup)
    // ---- Phase A: S = Q . K2^T ----
    const int wm = wid >> 2, wn = wid & 3;   // 4x4 warp grid, 32m x 64n tiles
    float acc[2][8][4];
#pragma unroll
    for (int mt = 0; mt < 2; mt++)
#pragma unroll
        for (int nt = 0; nt < 8; nt++)
#pragma unroll
            for (int r = 0; r < 4; r++) acc[mt][nt][r] = 0.f;

    const __half* Qg = qk + qrow0 * 1024;

    auto stage = [&](int c, int bi) {
        __half* sQ = Qb[bi];
        __half* sK = Kb[bi];
#pragma unroll
        for (int l = 0; l < 2; l++) {
            int idx = tid + l * 512;        // 0..1023: 128 rows x 8 x 16B
            int row = idx >> 3, q = idx & 7;
            cpa16(smem_u32(sQ + row * ASTRH + q * 8),
                  Qg + (size_t)row * 1024 + c * 64 + q * 8);
        }
#pragma unroll
        for (int l = 0; l < 4; l++) {
            int idx = tid + l * 512;        // 0..2047: 256 rows x 8 x 16B
            int row = idx >> 3, q = idx & 7;
            const __half* src = qk + (qrow0 + row - 128) * 1024 + 512 + c * 64 + q * 8;
            int sz = (w0 && row < 128) ? 0 : 16;
            cpa16z(smem_u32(sK + row * ASTRH + q * 8), (w0 && row < 128) ? qk : src, sz);
        }
    };

    auto stageC = [&](int c, int bi) {
        __half* dst = Kc + bi * 18432;
#pragma unroll
        for (int l = 0; l < 4; l++) {
            int idx = tid + l * 512;
            int row = idx >> 3, q = idx & 7;
            const __half* src = qk + (qrow0 + row - 128) * 1024 + 512 + c * 64 + q * 8;
            int sz = (w0 && row < 128) ? 0 : 16;
            cpa16z(smem_u32(dst + row * CSTRH + q * 8), (w0 && row < 128) ? qk : src, sz);
        }
    };

    stage(0, 0);
    asm volatile("cp.async.commit_group;" ::: "memory");

    for (int c = 0; c < 8; c++) {
        if (c + 1 < 8) {
            stage(c + 1, (c + 1) & 1);
            asm volatile("cp.async.commit_group;" ::: "memory");
            asm volatile("cp.async.wait_group 1;" ::: "memory");
        } else {
            asm volatile("cp.async.wait_group 0;" ::: "memory");
        }
        __syncthreads();

        const __half* sQ = Qb[c & 1];
        const __half* sK = Kb[c & 1];
#pragma unroll
        for (int s = 0; s < 4; s++) {        // 4 k16 per 64-d chunk
            const int kb = s * 16;
            uint32_t af[2][4], bf[8][2];
#pragma unroll
            for (int mt = 0; mt < 2; mt++)
                ldsm_x4(af[mt], smem_u32(sQ + (wm * 32 + mt * 16 + aRow) * ASTRH
                                            + kb + aKof));
#pragma unroll
            for (int np = 0; np < 4; np++) {
                uint32_t r4[4];
                ldsm_x4(r4, smem_u32(sK + (wn * 64 + np * 16 + bRow) * ASTRH
                                        + kb + bKof));
                bf[np * 2 + 0][0] = r4[0]; bf[np * 2 + 0][1] = r4[1];
                bf[np * 2 + 1][0] = r4[2]; bf[np * 2 + 1][1] = r4[3];
            }
#pragma unroll
            for (int mt = 0; mt < 2; mt++)
#pragma unroll
                for (int nt = 0; nt < 8; nt++)
                    mma_f16(acc[mt][nt], af[mt], bf[nt]);
        }
        __syncthreads();
    }

    // Prefetch phase-C chunk 0 (Kc disjoint from Ps; overlaps S->Ps + softmax).
    stageC(0, 0);
    asm volatile("cp.async.commit_group;" ::: "memory");

    // S -> Ps (fp32)
#pragma unroll
    for (int mt = 0; mt < 2; mt++) {
        int row = wm * 32 + mt * 16 + gid;
#pragma unroll
        for (int nt = 0; nt < 8; nt++) {
            int col = wn * 64 + nt * 8 + 2 * tig;
            *(float2*)(Ps + row * PSTR + col) =
                make_float2(acc[mt][nt][0], acc[mt][nt][1]);
            *(float2*)(Ps + (row + 8) * PSTR + col) =
                make_float2(acc[mt][nt][2], acc[mt][nt][3]);
        }
    }
    __syncthreads();

    // ---- softmax: 32 row-groups (tr) x 4 rows; cols j = cj*16 + tc ----
    {
        const float scale = 0.04419417382415922f;   // 512^-0.5
        const int tr = tid >> 4, tc = tid & 15;
#pragma unroll
        for (int ri = 0; ri < 4; ri++) {
            int i = tr * 4 + ri;
            float* prow = Ps + i * PSTR;
            float vv[16];
            float mx = -3.402823466e38f;
#pragma unroll
            for (int cj = 0; cj < 16; cj++) {
                int j = cj * 16 + tc;
                float v = prow[j] * scale;
                if (j > i + 128) v = -3.402823466e38f;
                vv[cj] = v;
                mx = fmaxf(mx, v);
            }
#pragma unroll
            for (int m = 8; m >= 1; m >>= 1)
                mx = fmaxf(mx, __shfl_xor_sync(0xffffffffu, mx, m));
            float sum = 0.f;
#pragma unroll
            for (int cj = 0; cj < 16; cj++) {
                vv[cj] = __expf(vv[cj] - mx);
                sum += vv[cj];
            }
#pragma unroll
            for (int m = 8; m >= 1; m >>= 1)
                sum += __shfl_xor_sync(0xffffffffu, sum, m);
            float inv = 1.f / sum;
            __syncwarp();                    // fp32 reads done before fp16 writes
            __half* ph = (__half*)prow;
#pragma unroll
            for (int cj = 0; cj < 16; cj++)
                ph[cj * 16 + tc] = __float2half_rn(vv[cj] * inv);
        }
    }
    __syncthreads();

    // ---- Phase C: O = P . K2 (fp16), 8 chunks of 64 d-cols; warp grid 4x4 ----
    const int wm2 = wid >> 2, wn2 = wid & 3;   // 32m x 16d warp tiles
    const __half* Ph = (const __half*)Ps;
    for (int co = 0; co < 8; co++) {
        if (co + 1 < 8) {
            stageC(co + 1, (co + 1) & 1);
            asm volatile("cp.async.commit_group;" ::: "memory");
            asm volatile("cp.async.wait_group 1;" ::: "memory");
        } else {
            asm volatile("cp.async.wait_group 0;" ::: "memory");
        }
        __syncthreads();

        const __half* Kcb = Kc + (co & 1) * 18432;
        float a2[2][2][4];
#pragma unroll
        for (int mt = 0; mt < 2; mt++)
#pragma unroll
            for (int nt = 0; nt < 2; nt++)
#pragma unroll
                for (int r = 0; r < 4; r++) a2[mt][nt][r] = 0.f;

#pragma unroll 4
        for (int k16 = 0; k16 < 16; k16++) {
            const int kb = k16 * 16;
            uint32_t af[2][4], bf[2][2];
#pragma unroll
            for (int mt = 0; mt < 2; mt++)
                ldsm_x4(af[mt], smem_u32(Ph + (wm2 * 32 + mt * 16 + aRow) * PSTRH
                                            + kb + aKof));
#pragma unroll
            for (int nt = 0; nt < 2; nt++)
                ldsm_x2t(bf[nt], smem_u32(Kcb + (kb + tRow) * CSTRH
                                              + wn2 * 16 + nt * 8));
#pragma unroll
            for (int mt = 0; mt < 2; mt++)
#pragma unroll
                for (int nt = 0; nt < 2; nt++)
                    mma_f16(a2[mt][nt], af[mt], bf[nt]);
        }

        int c0 = co * 64;
#pragma unroll
        for (int mt = 0; mt < 2; mt++) {
            size_t row = qrow0 + wm2 * 32 + mt * 16 + gid;
#pragma unroll
            for (int nt = 0; nt < 2; nt++) {
                int col = c0 + wn2 * 16 + nt * 8 + 2 * tig;
                *(__half2*)(ao + row * 512 + col) =
                    __floats2half2_rn(a2[mt][nt][0], a2[mt][nt][1]);
                *(__half2*)(ao + (row + 8) * 512 + col) =
                    __floats2half2_rn(a2[mt][nt][2], a2[mt][nt][3]);
            }
        }
        __syncthreads();
    }
}

// ---------------------------------------------------------------------------
extern "C" void kernel_launch(void* const* d_in, const int* in_sizes, int n_in,
                              void* d_out, int out_size)
{
    (void)in_sizes; (void)n_in; (void)out_size;
    const float* x     = (const float*)d_in[0];   // (4,8192,512)
    const float* w_qkv = (const float*)d_in[1];   // (1536,512); rows 0..1023 used
    const float* w_out = (const float*)d_in[2];   // (512,512)
    const float* b_out = (const float*)d_in[3];   // (512,)
    float* out = (float*)d_out;                   // (4,8192,512)

    __half *qkh, *aoh, *xh, *wh, *woh;
    cudaGetSymbolAddress((void**)&qkh, g_qkh);
    cudaGetSymbolAddress((void**)&aoh, g_aoh);
    cudaGetSymbolAddress((void**)&xh,  g_xh);
    cudaGetSymbolAddress((void**)&wh,  g_wh);
    cudaGetSymbolAddress((void**)&woh, g_woh);

    cudaFuncSetAttribute(attn_mma,
                         cudaFuncAttributeMaxDynamicSharedMemorySize, 206848);
    cudaFuncSetAttribute((const void*)hgemm<true, false>,
                         cudaFuncAttributeMaxDynamicSharedMemorySize, 73728);
    cudaFuncSetAttribute((const void*)hgemm<false, true>,
                         cudaFuncAttributeMaxDynamicSharedMemorySize, 73728);

    // 0) Convert operands to fp16.
    f2h_k<<<(4194304 + 255) / 256, 256>>>((const float4*)x, (uint2*)xh, 4194304);
    f2h_k<<<(131072  + 255) / 256, 256>>>((const float4*)w_qkv, (uint2*)wh, 131072);
    f2h_k<<<(65536   + 255) / 256, 256>>>((const float4*)w_out, (uint2*)woh, 65536);

    // 1) QK projection (fp16 in, fp16 out). V is dead in the reference.
    {
        dim3 g(1024 / 128, 32768 / 128);
        hgemm<true, false><<<g, 256, 73728>>>(xh, wh, nullptr, qkh, 1024, 512);
    }

    // 2) fp16 tensor-core windowed attention (256 windows, 512 threads).
    attn_mma<<<256, 512, 206848>>>(qkh, aoh);

    // 3) Output projection + bias (fp16 in, fp32 out).
    {
        dim3 g(512 / 128, 32768 / 128);
        hgemm<false, true><<<g, 256, 73728>>>(aoh, woh, b_out, out, 512, 512);
    }
}